// round 2
// baseline (speedup 1.0000x reference)
#include <cuda_runtime.h>
#include <cuda_bf16.h>
#include <math.h>

#define T_SEQ 4096
#define HIDDEN 2048
#define NHEADS 16
#define HEAD_DIM 128
#define SOFTCAP 50.0f
#define ATT_SCALE 0.0625f   // 256^-0.5

// ---------------- scratch (device globals; allocation-free) ----------------
// g_qkv: [3][T][HIDDEN]  (q, k, v post-projection; RoPE applied in place to q,k)
// g_att: [T][HIDDEN]     (attention output, pre-Wo)
__device__ float g_qkv[3u * T_SEQ * HIDDEN];
__device__ float g_att[(size_t)T_SEQ * HIDDEN];

// ---------------- SGEMM: C[M,N] = A[M,K] @ B[K,N], fp32 -------------------
// BM=BN=128, BK=16, 256 threads, 8x8 register tile per thread.
#define BM 128
#define BN 128
#define BK 16

__global__ __launch_bounds__(256) void sgemm_kernel(
    const float* __restrict__ A, const float* __restrict__ B,
    float* __restrict__ C, int M, int N, int K)
{
    __shared__ float As[BK][BM + 4];   // transposed A tile, padded
    __shared__ float Bs[BK][BN];

    const int tid = threadIdx.x;
    const int tx = tid & 15;           // 0..15  -> N direction
    const int ty = tid >> 4;           // 0..15  -> M direction
    const int bm = blockIdx.y * BM;
    const int bn = blockIdx.x * BN;

    // A-load mapping: 128 rows x 16 cols, float4 per thread, 2 passes
    const int arow = tid >> 2;          // 0..63
    const int acol = (tid & 3) * 4;     // 0,4,8,12
    // B-load mapping: 16 rows x 128 cols, float4 per thread, 2 passes
    const int brow = tid >> 5;          // 0..7
    const int bcol = (tid & 31) * 4;

    float acc[8][8];
#pragma unroll
    for (int i = 0; i < 8; i++)
#pragma unroll
        for (int j = 0; j < 8; j++) acc[i][j] = 0.f;

    for (int k0 = 0; k0 < K; k0 += BK) {
#pragma unroll
        for (int p = 0; p < 2; p++) {
            int r = arow + p * 64;
            float4 va = *(const float4*)&A[(size_t)(bm + r) * K + k0 + acol];
            As[acol + 0][r] = va.x;
            As[acol + 1][r] = va.y;
            As[acol + 2][r] = va.z;
            As[acol + 3][r] = va.w;
        }
#pragma unroll
        for (int p = 0; p < 2; p++) {
            int r = brow + p * 8;
            *(float4*)&Bs[r][bcol] = *(const float4*)&B[(size_t)(k0 + r) * N + bn + bcol];
        }
        __syncthreads();

#pragma unroll
        for (int kk = 0; kk < BK; kk++) {
            float a[8], b[8];
#pragma unroll
            for (int i = 0; i < 8; i++) a[i] = As[kk][ty * 8 + i];   // broadcast
            float4 b0 = *(const float4*)&Bs[kk][tx * 8];
            float4 b1 = *(const float4*)&Bs[kk][tx * 8 + 4];
            b[0]=b0.x; b[1]=b0.y; b[2]=b0.z; b[3]=b0.w;
            b[4]=b1.x; b[5]=b1.y; b[6]=b1.z; b[7]=b1.w;
#pragma unroll
            for (int i = 0; i < 8; i++)
#pragma unroll
                for (int j = 0; j < 8; j++)
                    acc[i][j] += a[i] * b[j];
        }
        __syncthreads();
    }

#pragma unroll
    for (int i = 0; i < 8; i++) {
        float4 o0 = make_float4(acc[i][0], acc[i][1], acc[i][2], acc[i][3]);
        float4 o1 = make_float4(acc[i][4], acc[i][5], acc[i][6], acc[i][7]);
        size_t row = (size_t)(bm + ty * 8 + i) * N + bn + tx * 8;
        *(float4*)&C[row]     = o0;
        *(float4*)&C[row + 4] = o1;
    }
}

// ---------------- RoPE (in place on q and k) -------------------------------
// One thread per (w in {q,k}, t, h, d<64) pair — owns both halves, no race.
__global__ __launch_bounds__(256) void rope_kernel()
{
    int idx = blockIdx.x * blockDim.x + threadIdx.x;   // 2*4096*16*64 total
    int d = idx & 63;
    int h = (idx >> 6) & 15;
    int t = (idx >> 10) & (T_SEQ - 1);
    int w = idx >> 22;                                 // 0=q, 1=k
    float* base = g_qkv + (size_t)w * T_SEQ * HIDDEN + (size_t)t * HIDDEN + h * HEAD_DIM;

    // inv_freq[i] = 10000^(-i/64), matching arange(0,128,2)/128
    float inv_freq = powf(10000.0f, -(float)d * (1.0f / 64.0f));
    float ang = (float)t * inv_freq;
    float c = cosf(ang), s = sinf(ang);

    float x1 = base[d];
    float x2 = base[d + 64];
    base[d]      = x1 * c - x2 * s;
    base[d + 64] = x2 * c + x1 * s;
}

// ---------------- Flash attention (fp32, no running max needed) ------------
// Block: (qb, h). BQ=BK=32, 256 threads.
// Thread (r = tid>>3, g = tid&7):
//   S phase: owns S[r][j] for j in {g, g+8, g+16, g+24}
//   O phase: owns O[r][d] for d in {32*i + 4*g + c}, i<4, c<4
#define FA_PAD 132

__global__ __launch_bounds__(256) void flash_attn_kernel()
{
    const float* Q = g_qkv;
    const float* K = g_qkv + (size_t)T_SEQ * HIDDEN;
    const float* V = g_qkv + 2u * T_SEQ * HIDDEN;

    __shared__ float Qs[32][FA_PAD];
    __shared__ float KVs[32][FA_PAD];
    __shared__ float Ps[32][36];

    const int tid = threadIdx.x;
    const int h  = blockIdx.y;
    const int qb = blockIdx.x;
    const int r  = tid >> 3;
    const int g  = tid & 7;
    const int qidx = qb * 32 + r;

    // Load Q tile: row r, cols {32i + 4g .. +3}
    {
        size_t rowQ = (size_t)qidx * HIDDEN + h * HEAD_DIM;
#pragma unroll
        for (int i = 0; i < 4; i++)
            *(float4*)&Qs[r][32 * i + 4 * g] = *(const float4*)&Q[rowQ + 32 * i + 4 * g];
    }

    float acc[16];
#pragma unroll
    for (int i = 0; i < 16; i++) acc[i] = 0.f;
    float denom = 0.f;

    for (int kb = 0; kb <= qb; kb++) {
        const size_t rowKV = (size_t)(kb * 32 + r) * HIDDEN + h * HEAD_DIM;

        __syncthreads();   // prior PV reads of KVs done; (first iter: Qs visible)
#pragma unroll
        for (int i = 0; i < 4; i++)
            *(float4*)&KVs[r][32 * i + 4 * g] = *(const float4*)&K[rowKV + 32 * i + 4 * g];
        __syncthreads();

        // S = Q K^T for this thread's 4 j's (stride-8 mapping -> conflict-free)
        float s0 = 0.f, s1 = 0.f, s2 = 0.f, s3 = 0.f;
#pragma unroll 4
        for (int d = 0; d < HEAD_DIM; d++) {
            float q = Qs[r][d];
            s0 += q * KVs[g][d];
            s1 += q * KVs[g + 8][d];
            s2 += q * KVs[g + 16][d];
            s3 += q * KVs[g + 24][d];
        }

        float sv[4] = {s0, s1, s2, s3};
#pragma unroll
        for (int jj = 0; jj < 4; jj++) {
            int j = g + 8 * jj;
            int kidx = kb * 32 + j;
            float a = sv[jj] * (ATT_SCALE / SOFTCAP);
            a = tanhf(a) * SOFTCAP;
            float e = (kidx <= qidx) ? expf(a) : 0.f;
            Ps[r][j] = e;
        }
        __syncthreads();   // Ps visible AND all K reads done

        // Load V over KVs
#pragma unroll
        for (int i = 0; i < 4; i++)
            *(float4*)&KVs[r][32 * i + 4 * g] = *(const float4*)&V[rowKV + 32 * i + 4 * g];
        __syncthreads();

        // O += P V   (thread owns row r, 16 cols)
#pragma unroll 4
        for (int j = 0; j < 32; j++) {
            float p = Ps[r][j];
            denom += p;
#pragma unroll
            for (int i = 0; i < 4; i++) {
                float4 v4 = *(const float4*)&KVs[j][32 * i + 4 * g];
                acc[4 * i + 0] += p * v4.x;
                acc[4 * i + 1] += p * v4.y;
                acc[4 * i + 2] += p * v4.z;
                acc[4 * i + 3] += p * v4.w;
            }
        }
    }

    float inv = 1.0f / denom;
    size_t rowO = (size_t)qidx * HIDDEN + h * HEAD_DIM;
#pragma unroll
    for (int i = 0; i < 4; i++) {
        float4 o = make_float4(acc[4*i+0]*inv, acc[4*i+1]*inv, acc[4*i+2]*inv, acc[4*i+3]*inv);
        *(float4*)&g_att[rowO + 32 * i + 4 * g] = o;
    }
}

// ---------------- launch ----------------------------------------------------
extern "C" void kernel_launch(void* const* d_in, const int* in_sizes, int n_in,
                              void* d_out, int out_size)
{
    const float* X  = (const float*)d_in[0];
    const float* Wq = (const float*)d_in[1];
    const float* Wk = (const float*)d_in[2];
    const float* Wv = (const float*)d_in[3];
    const float* Wo = (const float*)d_in[4];
    float* out = (float*)d_out;

    float* qkv;
    cudaGetSymbolAddress((void**)&qkv, g_qkv);
    float* att;
    cudaGetSymbolAddress((void**)&att, g_att);

    float* q = qkv;
    float* k = qkv + (size_t)T_SEQ * HIDDEN;
    float* v = qkv + 2u * T_SEQ * HIDDEN;

    dim3 gg(HIDDEN / BN, T_SEQ / BM);     // (16, 32)
    sgemm_kernel<<<gg, 256>>>(X, Wq, q, T_SEQ, HIDDEN, HIDDEN);
    sgemm_kernel<<<gg, 256>>>(X, Wk, k, T_SEQ, HIDDEN, HIDDEN);
    sgemm_kernel<<<gg, 256>>>(X, Wv, v, T_SEQ, HIDDEN, HIDDEN);

    // 2 * 4096 * 16 * 64 = 8388608 threads
    rope_kernel<<<8388608 / 256, 256>>>();

    flash_attn_kernel<<<dim3(T_SEQ / 32, NHEADS), 256>>>();

    sgemm_kernel<<<gg, 256>>>(att, Wo, out, T_SEQ, HIDDEN, HIDDEN);
}

// round 4
// speedup vs baseline: 2.0129x; 2.0129x over previous
#include <cuda_runtime.h>
#include <cuda_bf16.h>
#include <cstdint>
#include <math.h>

#define T_SEQ 4096
#define HIDDEN 2048
#define NHEADS 16
#define HEAD_DIM 128
#define SOFTCAP 50.0f
#define ATT_SCALE 0.0625f   // 256^-0.5

// ---------------- scratch (device globals; allocation-free) ----------------
__device__ float g_qkv[3u * T_SEQ * HIDDEN];
__device__ float g_att[(size_t)T_SEQ * HIDDEN];
__device__ __nv_bfloat16 g_xh[(size_t)T_SEQ * HIDDEN];
__device__ __nv_bfloat16 g_xl[(size_t)T_SEQ * HIDDEN];
__device__ __nv_bfloat16 g_ah[(size_t)T_SEQ * HIDDEN];
__device__ __nv_bfloat16 g_al[(size_t)T_SEQ * HIDDEN];
__device__ __nv_bfloat16 g_wth[4u * HIDDEN * HIDDEN];
__device__ __nv_bfloat16 g_wtl[4u * HIDDEN * HIDDEN];

// ======================= PTX helpers =======================================
__device__ __forceinline__ uint32_t smem_u32(const void* p) {
    uint32_t a;
    asm("{ .reg .u64 t; cvta.to.shared.u64 t, %1; cvt.u32.u64 %0, t; }"
        : "=r"(a) : "l"(p));
    return a;
}
__device__ __forceinline__ void cp_async16(uint32_t s, const void* g) {
    asm volatile("cp.async.cg.shared.global [%0], [%1], 16;" :: "r"(s), "l"(g));
}
#define CP_COMMIT() asm volatile("cp.async.commit_group;" ::: "memory")
#define CP_WAIT1()  asm volatile("cp.async.wait_group 1;" ::: "memory")

__device__ __forceinline__ void ldmx4(uint32_t* r, uint32_t addr) {
    asm volatile("ldmatrix.sync.aligned.m8n8.x4.shared.b16 {%0,%1,%2,%3}, [%4];"
        : "=r"(r[0]), "=r"(r[1]), "=r"(r[2]), "=r"(r[3]) : "r"(addr));
}
__device__ __forceinline__ void mma_bf16(float* d, const uint32_t* a,
                                         uint32_t b0, uint32_t b1) {
    asm volatile("mma.sync.aligned.m16n8k16.row.col.f32.bf16.bf16.f32 "
        "{%0,%1,%2,%3}, {%4,%5,%6,%7}, {%8,%9}, {%0,%1,%2,%3};"
        : "+f"(d[0]), "+f"(d[1]), "+f"(d[2]), "+f"(d[3])
        : "r"(a[0]), "r"(a[1]), "r"(a[2]), "r"(a[3]), "r"(b0), "r"(b1));
}

// ---------------- split conversions ----------------------------------------
__global__ __launch_bounds__(256) void cvt_split(const float* __restrict__ in,
                                                 __nv_bfloat16* __restrict__ oh,
                                                 __nv_bfloat16* __restrict__ ol) {
    int i = (blockIdx.x * 256 + threadIdx.x) * 4;
    float4 v = *(const float4*)&in[i];
    float x[4] = {v.x, v.y, v.z, v.w};
#pragma unroll
    for (int j = 0; j < 4; j++) {
        __nv_bfloat16 h = __float2bfloat16(x[j]);
        oh[i + j] = h;
        ol[i + j] = __float2bfloat16(x[j] - __bfloat162float(h));
    }
}

// transpose 2048x2048 fp32 -> bf16 hi/lo at [n][k]
__global__ __launch_bounds__(256) void transpose_split(const float* __restrict__ in,
                                                       __nv_bfloat16* __restrict__ oh,
                                                       __nv_bfloat16* __restrict__ ol) {
    __shared__ float t[32][33];
    int x = blockIdx.x * 32 + threadIdx.x;
    int y = blockIdx.y * 32 + threadIdx.y;
#pragma unroll
    for (int j = 0; j < 4; j++)
        t[threadIdx.y + 8 * j][threadIdx.x] = in[(size_t)(y + 8 * j) * HIDDEN + x];
    __syncthreads();
    x = blockIdx.y * 32 + threadIdx.x;           // k
    y = blockIdx.x * 32 + threadIdx.y;           // n
#pragma unroll
    for (int j = 0; j < 4; j++) {
        float v = t[threadIdx.x][threadIdx.y + 8 * j];
        __nv_bfloat16 h = __float2bfloat16(v);
        size_t o = (size_t)(y + 8 * j) * HIDDEN + x;
        oh[o] = h;
        ol[o] = __float2bfloat16(v - __bfloat162float(h));
    }
}

// ---------------- bf16x3 mma.sync GEMM -------------------------------------
// C[4096,2048] = A @ B^T with A=(Ah+Al), B=(Bh+Bl); D += AhBh + AlBh + AhBl.
// Tile 128x128, BK=32, 3-stage cp.async pipeline, 8 warps (2m x 4n), warp 64x32.
// smem per stage: Ah,Al,Bh,Bl each 128 rows x 32 bf16, row stride 80B = 10240B.
#define GS_AH 0
#define GS_AL 10240
#define GS_BH 20480
#define GS_BL 30720
#define GS_STAGE 40960
#define GS_TOTAL (3 * GS_STAGE)
#define G_KCHUNKS (HIDDEN / 32)

__global__ __launch_bounds__(256) void gemm_mma(
    const __nv_bfloat16* __restrict__ Ah, const __nv_bfloat16* __restrict__ Al,
    const __nv_bfloat16* __restrict__ Bh, const __nv_bfloat16* __restrict__ Bl,
    float* __restrict__ C)
{
    extern __shared__ char sm[];
    const uint32_t sb = smem_u32(sm);
    const int tid = threadIdx.x;
    const int lane = tid & 31;
    const int wid = tid >> 5;
    const int wm = wid & 1;          // 0..1  (64 rows each)
    const int wn = wid >> 1;         // 0..3  (32 cols each)
    const int bm = blockIdx.y * 128;
    const int bn = blockIdx.x * 128;

    float acc[4][4][4];
#pragma unroll
    for (int a = 0; a < 4; a++)
#pragma unroll
        for (int b = 0; b < 4; b++)
#pragma unroll
            for (int c = 0; c < 4; c++) acc[a][b][c] = 0.f;

    auto issue = [&](int chunk) {
        uint32_t st = sb + (chunk % 3) * GS_STAGE;
        int k0 = chunk * 32;
#pragma unroll
        for (int p = 0; p < 2; p++) {
            int idx = tid + p * 256;
            int row = idx >> 2, c = idx & 3;
            uint32_t soff = row * 80 + c * 16;
            size_t ga = (size_t)(bm + row) * HIDDEN + k0 + c * 8;
            size_t gb = (size_t)(bn + row) * HIDDEN + k0 + c * 8;
            cp_async16(st + GS_AH + soff, Ah + ga);
            cp_async16(st + GS_AL + soff, Al + ga);
            cp_async16(st + GS_BH + soff, Bh + gb);
            cp_async16(st + GS_BL + soff, Bl + gb);
        }
    };

    issue(0); CP_COMMIT();
    issue(1); CP_COMMIT();

    // ldmatrix per-lane base offsets (bytes)
    const uint32_t aBase = (uint32_t)(wm * 64 + (lane & 15)) * 80 + (lane >> 4) * 16;
    const uint32_t bBase = (uint32_t)(wn * 32 + ((lane >> 4) & 1) * 8 + (lane & 7)) * 80
                         + ((lane >> 3) & 1) * 16;

    for (int i = 0; i < G_KCHUNKS; i++) {
        CP_WAIT1();
        __syncthreads();
        uint32_t st = sb + (i % 3) * GS_STAGE;
#pragma unroll
        for (int kk = 0; kk < 2; kk++) {
            uint32_t aH[4][4], aL[4][4], bH[2][4], bL[2][4];
#pragma unroll
            for (int mt = 0; mt < 4; mt++) {
                ldmx4(aH[mt], st + GS_AH + aBase + mt * 1280 + kk * 32);
                ldmx4(aL[mt], st + GS_AL + aBase + mt * 1280 + kk * 32);
            }
#pragma unroll
            for (int np = 0; np < 2; np++) {
                ldmx4(bH[np], st + GS_BH + bBase + np * 1280 + kk * 32);
                ldmx4(bL[np], st + GS_BL + bBase + np * 1280 + kk * 32);
            }
#pragma unroll
            for (int mt = 0; mt < 4; mt++)
#pragma unroll
                for (int nt = 0; nt < 4; nt++) {
                    uint32_t b0h = bH[nt >> 1][(nt & 1) * 2];
                    uint32_t b1h = bH[nt >> 1][(nt & 1) * 2 + 1];
                    uint32_t b0l = bL[nt >> 1][(nt & 1) * 2];
                    uint32_t b1l = bL[nt >> 1][(nt & 1) * 2 + 1];
                    mma_bf16(acc[mt][nt], aH[mt], b0h, b1h);
                    mma_bf16(acc[mt][nt], aL[mt], b0h, b1h);
                    mma_bf16(acc[mt][nt], aH[mt], b0l, b1l);
                }
        }
        if (i + 2 < G_KCHUNKS) issue(i + 2);
        CP_COMMIT();
    }

    // epilogue: lane holds (g,2t),(g,2t+1),(g+8,2t),(g+8,2t+1) per 16x8 tile
    const int g = lane >> 2, t2 = (lane & 3) * 2;
#pragma unroll
    for (int mt = 0; mt < 4; mt++) {
        int mrow = bm + wm * 64 + mt * 16 + g;
#pragma unroll
        for (int nt = 0; nt < 4; nt++) {
            int ncol = bn + wn * 32 + nt * 8 + t2;
            *(float2*)&C[(size_t)mrow * HIDDEN + ncol] =
                make_float2(acc[mt][nt][0], acc[mt][nt][1]);
            *(float2*)&C[(size_t)(mrow + 8) * HIDDEN + ncol] =
                make_float2(acc[mt][nt][2], acc[mt][nt][3]);
        }
    }
}

// ---------------- RoPE (in place on q and k) -------------------------------
__global__ __launch_bounds__(256) void rope_kernel() {
    int idx = blockIdx.x * blockDim.x + threadIdx.x;
    int d = idx & 63;
    int h = (idx >> 6) & 15;
    int t = (idx >> 10) & (T_SEQ - 1);
    int w = idx >> 22;
    float* base = g_qkv + (size_t)w * T_SEQ * HIDDEN + (size_t)t * HIDDEN + h * HEAD_DIM;
    float inv_freq = powf(10000.0f, -(float)d * (1.0f / 64.0f));
    float ang = (float)t * inv_freq;
    float c = cosf(ang), s = sinf(ang);
    float x1 = base[d];
    float x2 = base[d + 64];
    base[d]      = x1 * c - x2 * s;
    base[d + 64] = x2 * c + x1 * s;
}

// ---------------- Flash attention (fp32, 64x64 tiles) ----------------------
// 256 threads; thread (rq=tid>>4, cq=tid&15).
// S tile: rows {rq+16i}, cols {cq+16j}; O tile: rows {rq+16i}, cols {4cq, 64+4cq}.
#define FA_QS 0
#define FA_KV 8448
#define FA_PS 16896
#define FA_SMEM_BYTES ((16896 + 64 * 68) * 4)

__global__ __launch_bounds__(256) void flash_attn_kernel() {
    extern __shared__ float fsm[];
    float* Qs  = fsm + FA_QS;
    float* KVs = fsm + FA_KV;
    float* Ps  = fsm + FA_PS;

    const float* Q = g_qkv;
    const float* K = g_qkv + (size_t)T_SEQ * HIDDEN;
    const float* V = g_qkv + 2u * T_SEQ * HIDDEN;

    const int tid = threadIdx.x;
    const int h  = blockIdx.y;
    const int qb = (gridDim.x - 1) - blockIdx.x;    // heavy blocks first
    const int rq = tid >> 4;
    const int cq = tid & 15;

    const int lrow = tid >> 2;
    const int lcol = (tid & 3) * 4;

    {
        const float* src = &Q[(size_t)(qb * 64 + lrow) * HIDDEN + h * HEAD_DIM];
#pragma unroll
        for (int p = 0; p < 8; p++) {
            int col = lcol + 16 * p;
            *(float4*)&Qs[lrow * 132 + col] = *(const float4*)&src[col];
        }
    }

    float acc[4][8];
    float den[4];
#pragma unroll
    for (int i = 0; i < 4; i++) {
        den[i] = 0.f;
#pragma unroll
        for (int c = 0; c < 8; c++) acc[i][c] = 0.f;
    }

    for (int kb = 0; kb <= qb; kb++) {
        const float* ksrc = &K[(size_t)(kb * 64 + lrow) * HIDDEN + h * HEAD_DIM];
        const float* vsrc = &V[(size_t)(kb * 64 + lrow) * HIDDEN + h * HEAD_DIM];

        __syncthreads();
#pragma unroll
        for (int p = 0; p < 8; p++) {
            int col = lcol + 16 * p;
            *(float4*)&KVs[lrow * 132 + col] = *(const float4*)&ksrc[col];
        }
        __syncthreads();

        float s[4][4];
#pragma unroll
        for (int i = 0; i < 4; i++)
#pragma unroll
            for (int j = 0; j < 4; j++) s[i][j] = 0.f;

#pragma unroll 4
        for (int d = 0; d < HEAD_DIM; d += 4) {
            float4 qv[4], kv[4];
#pragma unroll
            for (int i = 0; i < 4; i++) qv[i] = *(float4*)&Qs[(rq + 16 * i) * 132 + d];
#pragma unroll
            for (int j = 0; j < 4; j++) kv[j] = *(float4*)&KVs[(cq + 16 * j) * 132 + d];
#pragma unroll
            for (int i = 0; i < 4; i++)
#pragma unroll
                for (int j = 0; j < 4; j++)
                    s[i][j] += qv[i].x * kv[j].x + qv[i].y * kv[j].y +
                               qv[i].z * kv[j].z + qv[i].w * kv[j].w;
        }

#pragma unroll
        for (int i = 0; i < 4; i++) {
            int qrow = rq + 16 * i;
            int qg = qb * 64 + qrow;
#pragma unroll
            for (int j = 0; j < 4; j++) {
                int krow = cq + 16 * j;
                int kg = kb * 64 + krow;
                float a = s[i][j] * (ATT_SCALE / SOFTCAP);
                float t2 = __expf(2.0f * a);
                float th = (t2 - 1.0f) / (t2 + 1.0f);
                float e = (kg <= qg) ? __expf(th * SOFTCAP) : 0.f;
                Ps[qrow * 68 + krow] = e;
            }
        }
        __syncthreads();

#pragma unroll
        for (int p = 0; p < 8; p++) {
            int col = lcol + 16 * p;
            *(float4*)&KVs[lrow * 132 + col] = *(const float4*)&vsrc[col];
        }
        __syncthreads();

#pragma unroll 2
        for (int j = 0; j < 64; j++) {
            float p0 = Ps[(rq +  0) * 68 + j];
            float p1 = Ps[(rq + 16) * 68 + j];
            float p2 = Ps[(rq + 32) * 68 + j];
            float p3 = Ps[(rq + 48) * 68 + j];
            den[0] += p0; den[1] += p1; den[2] += p2; den[3] += p3;
            float4 va = *(float4*)&KVs[j * 132 + 4 * cq];
            float4 vb = *(float4*)&KVs[j * 132 + 64 + 4 * cq];
            acc[0][0] += p0 * va.x; acc[0][1] += p0 * va.y; acc[0][2] += p0 * va.z; acc[0][3] += p0 * va.w;
            acc[0][4] += p0 * vb.x; acc[0][5] += p0 * vb.y; acc[0][6] += p0 * vb.z; acc[0][7] += p0 * vb.w;
            acc[1][0] += p1 * va.x; acc[1][1] += p1 * va.y; acc[1][2] += p1 * va.z; acc[1][3] += p1 * va.w;
            acc[1][4] += p1 * vb.x; acc[1][5] += p1 * vb.y; acc[1][6] += p1 * vb.z; acc[1][7] += p1 * vb.w;
            acc[2][0] += p2 * va.x; acc[2][1] += p2 * va.y; acc[2][2] += p2 * va.z; acc[2][3] += p2 * va.w;
            acc[2][4] += p2 * vb.x; acc[2][5] += p2 * vb.y; acc[2][6] += p2 * vb.z; acc[2][7] += p2 * vb.w;
            acc[3][0] += p3 * va.x; acc[3][1] += p3 * va.y; acc[3][2] += p3 * va.z; acc[3][3] += p3 * va.w;
            acc[3][4] += p3 * vb.x; acc[3][5] += p3 * vb.y; acc[3][6] += p3 * vb.z; acc[3][7] += p3 * vb.w;
        }
    }

#pragma unroll
    for (int i = 0; i < 4; i++) {
        float inv = 1.0f / den[i];
        size_t row = (size_t)(qb * 64 + rq + 16 * i) * HIDDEN + h * HEAD_DIM;
        *(float4*)&g_att[row + 4 * cq] =
            make_float4(acc[i][0] * inv, acc[i][1] * inv, acc[i][2] * inv, acc[i][3] * inv);
        *(float4*)&g_att[row + 64 + 4 * cq] =
            make_float4(acc[i][4] * inv, acc[i][5] * inv, acc[i][6] * inv, acc[i][7] * inv);
    }
}

// ---------------- launch ----------------------------------------------------
extern "C" void kernel_launch(void* const* d_in, const int* in_sizes, int n_in,
                              void* d_out, int out_size) {
    const float* X  = (const float*)d_in[0];
    const float* Wq = (const float*)d_in[1];
    const float* Wk = (const float*)d_in[2];
    const float* Wv = (const float*)d_in[3];
    const float* Wo = (const float*)d_in[4];
    float* out = (float*)d_out;

    float* qkv; cudaGetSymbolAddress((void**)&qkv, g_qkv);
    float* att; cudaGetSymbolAddress((void**)&att, g_att);
    __nv_bfloat16 *xh, *xl, *ah, *al, *wth, *wtl;
    cudaGetSymbolAddress((void**)&xh, g_xh);
    cudaGetSymbolAddress((void**)&xl, g_xl);
    cudaGetSymbolAddress((void**)&ah, g_ah);
    cudaGetSymbolAddress((void**)&al, g_al);
    cudaGetSymbolAddress((void**)&wth, g_wth);
    cudaGetSymbolAddress((void**)&wtl, g_wtl);

    float* q = qkv;
    float* k = qkv + (size_t)T_SEQ * HIDDEN;
    float* v = qkv + 2u * T_SEQ * HIDDEN;

    cudaFuncSetAttribute(gemm_mma, cudaFuncAttributeMaxDynamicSharedMemorySize, GS_TOTAL);
    cudaFuncSetAttribute(flash_attn_kernel, cudaFuncAttributeMaxDynamicSharedMemorySize,
                         FA_SMEM_BYTES);

    const size_t WSTRIDE = (size_t)HIDDEN * HIDDEN;
    dim3 tb(32, 8);
    dim3 tg(HIDDEN / 32, HIDDEN / 32);
    transpose_split<<<tg, tb>>>(Wq, wth + 0 * WSTRIDE, wtl + 0 * WSTRIDE);
    transpose_split<<<tg, tb>>>(Wk, wth + 1 * WSTRIDE, wtl + 1 * WSTRIDE);
    transpose_split<<<tg, tb>>>(Wv, wth + 2 * WSTRIDE, wtl + 2 * WSTRIDE);
    transpose_split<<<tg, tb>>>(Wo, wth + 3 * WSTRIDE, wtl + 3 * WSTRIDE);

    cvt_split<<<(T_SEQ * HIDDEN) / 1024, 256>>>(X, xh, xl);

    dim3 gg(HIDDEN / 128, T_SEQ / 128);   // (16, 32)
    gemm_mma<<<gg, 256, GS_TOTAL>>>(xh, xl, wth + 0 * WSTRIDE, wtl + 0 * WSTRIDE, q);
    gemm_mma<<<gg, 256, GS_TOTAL>>>(xh, xl, wth + 1 * WSTRIDE, wtl + 1 * WSTRIDE, k);
    gemm_mma<<<gg, 256, GS_TOTAL>>>(xh, xl, wth + 2 * WSTRIDE, wtl + 2 * WSTRIDE, v);

    rope_kernel<<<8388608 / 256, 256>>>();

    flash_attn_kernel<<<dim3(T_SEQ / 64, NHEADS), 256, FA_SMEM_BYTES>>>();

    cvt_split<<<(T_SEQ * HIDDEN) / 1024, 256>>>(att, ah, al);
    gemm_mma<<<gg, 256, GS_TOTAL>>>(ah, al, wth + 3 * WSTRIDE, wtl + 3 * WSTRIDE, out);
}

// round 5
// speedup vs baseline: 3.1503x; 1.5650x over previous
#include <cuda_runtime.h>
#include <cuda_bf16.h>
#include <cstdint>
#include <math.h>

#define T_SEQ 4096
#define HIDDEN 2048
#define NHEADS 16
#define HEAD_DIM 128
#define SOFTCAP 50.0f
#define ATT_SCALE 0.0625f   // 256^-0.5

// ---------------- scratch (device globals; allocation-free) ----------------
__device__ float g_qkv[3u * T_SEQ * HIDDEN];
__device__ __nv_bfloat16 g_xh[(size_t)T_SEQ * HIDDEN];
__device__ __nv_bfloat16 g_xl[(size_t)T_SEQ * HIDDEN];
__device__ __nv_bfloat16 g_ah[(size_t)T_SEQ * HIDDEN];
__device__ __nv_bfloat16 g_al[(size_t)T_SEQ * HIDDEN];
__device__ __nv_bfloat16 g_wth[4u * HIDDEN * HIDDEN];
__device__ __nv_bfloat16 g_wtl[4u * HIDDEN * HIDDEN];
// attention operand splits (post-RoPE)
__device__ __nv_bfloat16 g_qh[(size_t)T_SEQ * HIDDEN];
__device__ __nv_bfloat16 g_ql[(size_t)T_SEQ * HIDDEN];
__device__ __nv_bfloat16 g_kh[(size_t)T_SEQ * HIDDEN];
__device__ __nv_bfloat16 g_kl[(size_t)T_SEQ * HIDDEN];
__device__ __nv_bfloat16 g_vh[(size_t)T_SEQ * HIDDEN];
__device__ __nv_bfloat16 g_vl[(size_t)T_SEQ * HIDDEN];

// ======================= PTX helpers =======================================
__device__ __forceinline__ uint32_t smem_u32(const void* p) {
    uint32_t a;
    asm("{ .reg .u64 t; cvta.to.shared.u64 t, %1; cvt.u32.u64 %0, t; }"
        : "=r"(a) : "l"(p));
    return a;
}
__device__ __forceinline__ void cp_async16(uint32_t s, const void* g) {
    asm volatile("cp.async.cg.shared.global [%0], [%1], 16;" :: "r"(s), "l"(g));
}
#define CP_COMMIT() asm volatile("cp.async.commit_group;" ::: "memory")
#define CP_WAIT1()  asm volatile("cp.async.wait_group 1;" ::: "memory")
#define CP_WAIT0()  asm volatile("cp.async.wait_group 0;" ::: "memory")

__device__ __forceinline__ void ldmx4(uint32_t* r, uint32_t addr) {
    asm volatile("ldmatrix.sync.aligned.m8n8.x4.shared.b16 {%0,%1,%2,%3}, [%4];"
        : "=r"(r[0]), "=r"(r[1]), "=r"(r[2]), "=r"(r[3]) : "r"(addr));
}
__device__ __forceinline__ void ldmx4t(uint32_t* r, uint32_t addr) {
    asm volatile("ldmatrix.sync.aligned.m8n8.x4.trans.shared.b16 {%0,%1,%2,%3}, [%4];"
        : "=r"(r[0]), "=r"(r[1]), "=r"(r[2]), "=r"(r[3]) : "r"(addr));
}
__device__ __forceinline__ void mma_bf16(float* d, const uint32_t* a,
                                         uint32_t b0, uint32_t b1) {
    asm volatile("mma.sync.aligned.m16n8k16.row.col.f32.bf16.bf16.f32 "
        "{%0,%1,%2,%3}, {%4,%5,%6,%7}, {%8,%9}, {%0,%1,%2,%3};"
        : "+f"(d[0]), "+f"(d[1]), "+f"(d[2]), "+f"(d[3])
        : "r"(a[0]), "r"(a[1]), "r"(a[2]), "r"(a[3]), "r"(b0), "r"(b1));
}
__device__ __forceinline__ uint32_t pack_bf16(float lo, float hi) {
    __nv_bfloat162 v;
    v.x = __float2bfloat16(lo);
    v.y = __float2bfloat16(hi);
    return *(uint32_t*)&v;
}
// 256B-row xor swizzle (16B granules)
__device__ __forceinline__ uint32_t swz(int row, int cb) {
    return (uint32_t)(row * 256 + (cb ^ ((row & 7) * 16)));
}

// ---------------- split conversions ----------------------------------------
__global__ __launch_bounds__(256) void cvt_split(const float* __restrict__ in,
                                                 __nv_bfloat16* __restrict__ oh,
                                                 __nv_bfloat16* __restrict__ ol) {
    int i = (blockIdx.x * 256 + threadIdx.x) * 4;
    float4 v = *(const float4*)&in[i];
    float x[4] = {v.x, v.y, v.z, v.w};
#pragma unroll
    for (int j = 0; j < 4; j++) {
        __nv_bfloat16 h = __float2bfloat16(x[j]);
        oh[i + j] = h;
        ol[i + j] = __float2bfloat16(x[j] - __bfloat162float(h));
    }
}

// transpose 2048x2048 fp32 -> bf16 hi/lo at [n][k]
__global__ __launch_bounds__(256) void transpose_split(const float* __restrict__ in,
                                                       __nv_bfloat16* __restrict__ oh,
                                                       __nv_bfloat16* __restrict__ ol) {
    __shared__ float t[32][33];
    int x = blockIdx.x * 32 + threadIdx.x;
    int y = blockIdx.y * 32 + threadIdx.y;
#pragma unroll
    for (int j = 0; j < 4; j++)
        t[threadIdx.y + 8 * j][threadIdx.x] = in[(size_t)(y + 8 * j) * HIDDEN + x];
    __syncthreads();
    x = blockIdx.y * 32 + threadIdx.x;
    y = blockIdx.x * 32 + threadIdx.y;
#pragma unroll
    for (int j = 0; j < 4; j++) {
        float v = t[threadIdx.x][threadIdx.y + 8 * j];
        __nv_bfloat16 h = __float2bfloat16(v);
        size_t o = (size_t)(y + 8 * j) * HIDDEN + x;
        oh[o] = h;
        ol[o] = __float2bfloat16(v - __bfloat162float(h));
    }
}

// ---------------- bf16x3 mma.sync GEMM (unchanged from R4) -----------------
#define GS_AH 0
#define GS_AL 10240
#define GS_BH 20480
#define GS_BL 30720
#define GS_STAGE 40960
#define GS_TOTAL (3 * GS_STAGE)
#define G_KCHUNKS (HIDDEN / 32)

__global__ __launch_bounds__(256) void gemm_mma(
    const __nv_bfloat16* __restrict__ Ah, const __nv_bfloat16* __restrict__ Al,
    const __nv_bfloat16* __restrict__ Bh, const __nv_bfloat16* __restrict__ Bl,
    float* __restrict__ C)
{
    extern __shared__ char sm[];
    const uint32_t sb = smem_u32(sm);
    const int tid = threadIdx.x;
    const int lane = tid & 31;
    const int wid = tid >> 5;
    const int wm = wid & 1;
    const int wn = wid >> 1;
    const int bm = blockIdx.y * 128;
    const int bn = blockIdx.x * 128;

    float acc[4][4][4];
#pragma unroll
    for (int a = 0; a < 4; a++)
#pragma unroll
        for (int b = 0; b < 4; b++)
#pragma unroll
            for (int c = 0; c < 4; c++) acc[a][b][c] = 0.f;

    auto issue = [&](int chunk) {
        uint32_t st = sb + (chunk % 3) * GS_STAGE;
        int k0 = chunk * 32;
#pragma unroll
        for (int p = 0; p < 2; p++) {
            int idx = tid + p * 256;
            int row = idx >> 2, c = idx & 3;
            uint32_t soff = row * 80 + c * 16;
            size_t ga = (size_t)(bm + row) * HIDDEN + k0 + c * 8;
            size_t gb = (size_t)(bn + row) * HIDDEN + k0 + c * 8;
            cp_async16(st + GS_AH + soff, Ah + ga);
            cp_async16(st + GS_AL + soff, Al + ga);
            cp_async16(st + GS_BH + soff, Bh + gb);
            cp_async16(st + GS_BL + soff, Bl + gb);
        }
    };

    issue(0); CP_COMMIT();
    issue(1); CP_COMMIT();

    const uint32_t aBase = (uint32_t)(wm * 64 + (lane & 15)) * 80 + (lane >> 4) * 16;
    const uint32_t bBase = (uint32_t)(wn * 32 + ((lane >> 4) & 1) * 8 + (lane & 7)) * 80
                         + ((lane >> 3) & 1) * 16;

    for (int i = 0; i < G_KCHUNKS; i++) {
        CP_WAIT1();
        __syncthreads();
        uint32_t st = sb + (i % 3) * GS_STAGE;
#pragma unroll
        for (int kk = 0; kk < 2; kk++) {
            uint32_t aH[4][4], aL[4][4], bH[2][4], bL[2][4];
#pragma unroll
            for (int mt = 0; mt < 4; mt++) {
                ldmx4(aH[mt], st + GS_AH + aBase + mt * 1280 + kk * 32);
                ldmx4(aL[mt], st + GS_AL + aBase + mt * 1280 + kk * 32);
            }
#pragma unroll
            for (int np = 0; np < 2; np++) {
                ldmx4(bH[np], st + GS_BH + bBase + np * 1280 + kk * 32);
                ldmx4(bL[np], st + GS_BL + bBase + np * 1280 + kk * 32);
            }
#pragma unroll
            for (int mt = 0; mt < 4; mt++)
#pragma unroll
                for (int nt = 0; nt < 4; nt++) {
                    uint32_t b0h = bH[nt >> 1][(nt & 1) * 2];
                    uint32_t b1h = bH[nt >> 1][(nt & 1) * 2 + 1];
                    uint32_t b0l = bL[nt >> 1][(nt & 1) * 2];
                    uint32_t b1l = bL[nt >> 1][(nt & 1) * 2 + 1];
                    mma_bf16(acc[mt][nt], aH[mt], b0h, b1h);
                    mma_bf16(acc[mt][nt], aL[mt], b0h, b1h);
                    mma_bf16(acc[mt][nt], aH[mt], b0l, b1l);
                }
        }
        if (i + 2 < G_KCHUNKS) issue(i + 2);
        CP_COMMIT();
    }

    const int g = lane >> 2, t2 = (lane & 3) * 2;
#pragma unroll
    for (int mt = 0; mt < 4; mt++) {
        int mrow = bm + wm * 64 + mt * 16 + g;
#pragma unroll
        for (int nt = 0; nt < 4; nt++) {
            int ncol = bn + wn * 32 + nt * 8 + t2;
            *(float2*)&C[(size_t)mrow * HIDDEN + ncol] =
                make_float2(acc[mt][nt][0], acc[mt][nt][1]);
            *(float2*)&C[(size_t)(mrow + 8) * HIDDEN + ncol] =
                make_float2(acc[mt][nt][2], acc[mt][nt][3]);
        }
    }
}

// ---------------- fused RoPE + bf16 split for Q,K ---------------------------
__global__ __launch_bounds__(256) void rope_split_qk() {
    int idx = blockIdx.x * blockDim.x + threadIdx.x;   // 2*4096*16*64
    int d = idx & 63;
    int h = (idx >> 6) & 15;
    int t = (idx >> 10) & (T_SEQ - 1);
    int w = idx >> 22;                                  // 0=q, 1=k
    const float* src = g_qkv + (size_t)w * T_SEQ * HIDDEN
                     + (size_t)t * HIDDEN + h * HEAD_DIM;
    __nv_bfloat16* oh = (w == 0 ? g_qh : g_kh) + (size_t)t * HIDDEN + h * HEAD_DIM;
    __nv_bfloat16* ol = (w == 0 ? g_ql : g_kl) + (size_t)t * HIDDEN + h * HEAD_DIM;

    float inv_freq = powf(10000.0f, -(float)d * (1.0f / 64.0f));
    float ang = (float)t * inv_freq;
    float c = cosf(ang), s = sinf(ang);
    float x1 = src[d];
    float x2 = src[d + 64];
    float y1 = x1 * c - x2 * s;
    float y2 = x2 * c + x1 * s;
    __nv_bfloat16 h1 = __float2bfloat16(y1);
    __nv_bfloat16 h2 = __float2bfloat16(y2);
    oh[d] = h1;          ol[d] = __float2bfloat16(y1 - __bfloat162float(h1));
    oh[d + 64] = h2;     ol[d + 64] = __float2bfloat16(y2 - __bfloat162float(h2));
}

// ---------------- flash attention on mma.sync (bf16x3) ---------------------
// Block: 128 threads (4 warps), BQ=64 rows of head h; iterate 64-key tiles.
// Warp w owns q rows [16w,16w+16).  S tile per warp: 16x64 (8 n8-tiles).
// O tile per warp: 16x128 (16 n8-tiles). P stays in registers (frag relayout).
#define AT_KH 0
#define AT_KL 16384
#define AT_VH 32768
#define AT_VL 49152
#define AT_QH 65536
#define AT_QL 81920
#define AT_SMEM 98304

__global__ __launch_bounds__(128) void flash_mma() {
    extern __shared__ char sm[];
    const uint32_t sb = smem_u32(sm);
    const int tid = threadIdx.x;
    const int lane = tid & 31;
    const int w = tid >> 5;
    const int h = blockIdx.y;
    const int qb = (gridDim.x - 1) - blockIdx.x;       // heavy blocks first

    const int g = lane >> 2, t4 = lane & 3;

    // ---- load Q tile (hi/lo) into smem ----
    {
        int lrow = tid >> 1, cbase = (tid & 1) * 8;
        size_t gq = (size_t)(qb * 64 + lrow) * HIDDEN + h * HEAD_DIM;
#pragma unroll
        for (int j = 0; j < 8; j++) {
            int c = cbase + j;
            uint32_t off = swz(lrow, c * 16);
            cp_async16(sb + AT_QH + off, g_qh + gq + c * 8);
            cp_async16(sb + AT_QL + off, g_ql + gq + c * 8);
        }
        CP_COMMIT(); CP_WAIT0();
        __syncthreads();
    }

    // ---- preload qh A-fragments (8 k-steps) ----
    uint32_t qF[8][4];
    {
        int aRow = w * 16 + (lane & 15);
        int aHalf = (lane >> 4) * 16;
#pragma unroll
        for (int s = 0; s < 8; s++)
            ldmx4(qF[s], sb + AT_QH + swz(aRow, s * 32 + aHalf));
    }

    float O[16][4];
#pragma unroll
    for (int i = 0; i < 16; i++)
#pragma unroll
        for (int c = 0; c < 4; c++) O[i][c] = 0.f;
    float den0 = 0.f, den1 = 0.f;

    const int lrow = tid >> 1, cbase = (tid & 1) * 8;
    const int aRow = w * 16 + (lane & 15);
    const int aHalf = (lane >> 4) * 16;
    const int bRowBase = ((lane >> 4) & 1) * 8 + (lane & 7);
    const int bHalf = ((lane >> 3) & 1) * 16;
    const int vRowBase = ((lane >> 3) & 1) * 8 + (lane & 7);
    const int vHalf = ((lane >> 4) & 1) * 16;

    for (int kb = 0; kb <= qb; kb++) {
        __syncthreads();     // previous tile's smem fully consumed
        {
            size_t gk = (size_t)(kb * 64 + lrow) * HIDDEN + h * HEAD_DIM;
#pragma unroll
            for (int j = 0; j < 8; j++) {
                int c = cbase + j;
                uint32_t off = swz(lrow, c * 16);
                cp_async16(sb + AT_KH + off, g_kh + gk + c * 8);
                cp_async16(sb + AT_KL + off, g_kl + gk + c * 8);
                cp_async16(sb + AT_VH + off, g_vh + gk + c * 8);
                cp_async16(sb + AT_VL + off, g_vl + gk + c * 8);
            }
            CP_COMMIT(); CP_WAIT0();
            __syncthreads();
        }

        // ---- S = Q K^T (bf16x3) ----
        float S[8][4];
#pragma unroll
        for (int i = 0; i < 8; i++)
#pragma unroll
            for (int c = 0; c < 4; c++) S[i][c] = 0.f;

#pragma unroll
        for (int s = 0; s < 8; s++) {
            uint32_t qlF[4];
            ldmx4(qlF, sb + AT_QL + swz(aRow, s * 32 + aHalf));
            uint32_t bh[4][4], bl[4][4];
#pragma unroll
            for (int p = 0; p < 4; p++) {
                ldmx4(bh[p], sb + AT_KH + swz(bRowBase + p * 16, s * 32 + bHalf));
                ldmx4(bl[p], sb + AT_KL + swz(bRowBase + p * 16, s * 32 + bHalf));
            }
#pragma unroll
            for (int p = 0; p < 4; p++)
#pragma unroll
                for (int hf = 0; hf < 2; hf++) {
                    int nt = p * 2 + hf;
                    uint32_t b0 = bh[p][hf * 2], b1 = bh[p][hf * 2 + 1];
                    mma_bf16(S[nt], qF[s], b0, b1);
                    mma_bf16(S[nt], qlF, b0, b1);
                    mma_bf16(S[nt], qF[s], bl[p][hf * 2], bl[p][hf * 2 + 1]);
                }
        }

        // ---- softcap + causal + exp; split into ph/pl A-frags ----
        const int rowg = qb * 64 + w * 16 + g;
        const bool diag = (kb == qb);
#pragma unroll
        for (int nt = 0; nt < 8; nt++) {
#pragma unroll
            for (int c = 0; c < 4; c++) {
                float a = S[nt][c] * ATT_SCALE;
                float u = a * (2.0f / SOFTCAP);
                float e2 = __expf(u);
                float th = (e2 - 1.0f) / (e2 + 1.0f);
                float p = __expf(th * SOFTCAP);
                if (diag) {
                    int col = kb * 64 + nt * 8 + 2 * t4 + (c & 1);
                    int row = rowg + (c >> 1) * 8;
                    if (col > row) p = 0.f;
                }
                S[nt][c] = p;
                if (c < 2) den0 += p; else den1 += p;
            }
        }

        uint32_t pH[4][4], pL[4][4];
#pragma unroll
        for (int s2 = 0; s2 < 4; s2++) {
            float pf[8] = {S[2*s2][0], S[2*s2][1], S[2*s2][2], S[2*s2][3],
                           S[2*s2+1][0], S[2*s2+1][1], S[2*s2+1][2], S[2*s2+1][3]};
            float lo[8];
#pragma unroll
            for (int e = 0; e < 8; e++) {
                __nv_bfloat16 hb = __float2bfloat16(pf[e]);
                lo[e] = pf[e] - __bfloat162float(hb);
            }
            pH[s2][0] = pack_bf16(pf[0], pf[1]);
            pH[s2][1] = pack_bf16(pf[2], pf[3]);
            pH[s2][2] = pack_bf16(pf[4], pf[5]);
            pH[s2][3] = pack_bf16(pf[6], pf[7]);
            pL[s2][0] = pack_bf16(lo[0], lo[1]);
            pL[s2][1] = pack_bf16(lo[2], lo[3]);
            pL[s2][2] = pack_bf16(lo[4], lo[5]);
            pL[s2][3] = pack_bf16(lo[6], lo[7]);
        }

        // ---- O += P V (bf16x3), V B-frags via ldmatrix.trans ----
#pragma unroll
        for (int s2 = 0; s2 < 4; s2++) {
            int vRow = s2 * 16 + vRowBase;
#pragma unroll
            for (int dp = 0; dp < 8; dp++) {
                uint32_t vh4[4], vl4[4];
                ldmx4t(vh4, sb + AT_VH + swz(vRow, dp * 32 + vHalf));
                ldmx4t(vl4, sb + AT_VL + swz(vRow, dp * 32 + vHalf));
#pragma unroll
                for (int hf = 0; hf < 2; hf++) {
                    int dt = dp * 2 + hf;
                    uint32_t b0 = vh4[hf * 2], b1 = vh4[hf * 2 + 1];
                    mma_bf16(O[dt], pH[s2], b0, b1);
                    mma_bf16(O[dt], pL[s2], b0, b1);
                    mma_bf16(O[dt], pH[s2], vl4[hf * 2], vl4[hf * 2 + 1]);
                }
            }
        }
    }

    // ---- reduce denominators across the quad ----
    den0 += __shfl_xor_sync(0xFFFFFFFF, den0, 1);
    den0 += __shfl_xor_sync(0xFFFFFFFF, den0, 2);
    den1 += __shfl_xor_sync(0xFFFFFFFF, den1, 1);
    den1 += __shfl_xor_sync(0xFFFFFFFF, den1, 2);
    float inv0 = 1.0f / den0, inv1 = 1.0f / den1;

    // ---- write y split (bf16 hi/lo) directly ----
    const int row0 = qb * 64 + w * 16 + g;
    uint32_t* ahp = (uint32_t*)g_ah;
    uint32_t* alp = (uint32_t*)g_al;
#pragma unroll
    for (int dt = 0; dt < 16; dt++) {
        int col = h * HEAD_DIM + dt * 8 + 2 * t4;
        float v0 = O[dt][0] * inv0, v1 = O[dt][1] * inv0;
        float v2 = O[dt][2] * inv1, v3 = O[dt][3] * inv1;
        __nv_bfloat16 h0 = __float2bfloat16(v0), h1v = __float2bfloat16(v1);
        __nv_bfloat16 h2 = __float2bfloat16(v2), h3 = __float2bfloat16(v3);
        size_t o0 = ((size_t)row0 * HIDDEN + col) >> 1;
        size_t o1 = ((size_t)(row0 + 8) * HIDDEN + col) >> 1;
        ahp[o0] = pack_bf16(__bfloat162float(h0), __bfloat162float(h1v));
        alp[o0] = pack_bf16(v0 - __bfloat162float(h0), v1 - __bfloat162float(h1v));
        ahp[o1] = pack_bf16(__bfloat162float(h2), __bfloat162float(h3));
        alp[o1] = pack_bf16(v2 - __bfloat162float(h2), v3 - __bfloat162float(h3));
    }
}

// ---------------- launch ----------------------------------------------------
extern "C" void kernel_launch(void* const* d_in, const int* in_sizes, int n_in,
                              void* d_out, int out_size) {
    const float* X  = (const float*)d_in[0];
    const float* Wq = (const float*)d_in[1];
    const float* Wk = (const float*)d_in[2];
    const float* Wv = (const float*)d_in[3];
    const float* Wo = (const float*)d_in[4];
    float* out = (float*)d_out;

    float* qkv; cudaGetSymbolAddress((void**)&qkv, g_qkv);
    __nv_bfloat16 *xh, *xl, *ah, *al, *wth, *wtl, *vh, *vl;
    cudaGetSymbolAddress((void**)&xh, g_xh);
    cudaGetSymbolAddress((void**)&xl, g_xl);
    cudaGetSymbolAddress((void**)&ah, g_ah);
    cudaGetSymbolAddress((void**)&al, g_al);
    cudaGetSymbolAddress((void**)&wth, g_wth);
    cudaGetSymbolAddress((void**)&wtl, g_wtl);
    cudaGetSymbolAddress((void**)&vh, g_vh);
    cudaGetSymbolAddress((void**)&vl, g_vl);

    float* q = qkv;
    float* k = qkv + (size_t)T_SEQ * HIDDEN;
    float* v = qkv + 2u * T_SEQ * HIDDEN;

    cudaFuncSetAttribute(gemm_mma, cudaFuncAttributeMaxDynamicSharedMemorySize, GS_TOTAL);
    cudaFuncSetAttribute(flash_mma, cudaFuncAttributeMaxDynamicSharedMemorySize, AT_SMEM);

    const size_t WSTRIDE = (size_t)HIDDEN * HIDDEN;
    dim3 tb(32, 8);
    dim3 tg(HIDDEN / 32, HIDDEN / 32);
    transpose_split<<<tg, tb>>>(Wq, wth + 0 * WSTRIDE, wtl + 0 * WSTRIDE);
    transpose_split<<<tg, tb>>>(Wk, wth + 1 * WSTRIDE, wtl + 1 * WSTRIDE);
    transpose_split<<<tg, tb>>>(Wv, wth + 2 * WSTRIDE, wtl + 2 * WSTRIDE);
    transpose_split<<<tg, tb>>>(Wo, wth + 3 * WSTRIDE, wtl + 3 * WSTRIDE);

    cvt_split<<<(T_SEQ * HIDDEN) / 1024, 256>>>(X, xh, xl);

    dim3 gg(HIDDEN / 128, T_SEQ / 128);
    gemm_mma<<<gg, 256, GS_TOTAL>>>(xh, xl, wth + 0 * WSTRIDE, wtl + 0 * WSTRIDE, q);
    gemm_mma<<<gg, 256, GS_TOTAL>>>(xh, xl, wth + 1 * WSTRIDE, wtl + 1 * WSTRIDE, k);
    gemm_mma<<<gg, 256, GS_TOTAL>>>(xh, xl, wth + 2 * WSTRIDE, wtl + 2 * WSTRIDE, v);

    rope_split_qk<<<8388608 / 256, 256>>>();
    cvt_split<<<(T_SEQ * HIDDEN) / 1024, 256>>>(v, vh, vl);

    flash_mma<<<dim3(T_SEQ / 64, NHEADS), 128, AT_SMEM>>>();

    gemm_mma<<<gg, 256, GS_TOTAL>>>(ah, al, wth + 3 * WSTRIDE, wtl + 3 * WSTRIDE, out);
}

// round 6
// speedup vs baseline: 3.3926x; 1.0769x over previous
#include <cuda_runtime.h>
#include <cuda_bf16.h>
#include <cstdint>
#include <math.h>

#define T_SEQ 4096
#define HIDDEN 2048
#define NHEADS 16
#define HEAD_DIM 128
#define SOFTCAP 50.0f
#define ATT_SCALE 0.0625f   // 256^-0.5

// ---------------- scratch (device globals; allocation-free) ----------------
__device__ float g_qkv[3u * T_SEQ * HIDDEN];
__device__ __nv_bfloat16 g_xh[(size_t)T_SEQ * HIDDEN];
__device__ __nv_bfloat16 g_xl[(size_t)T_SEQ * HIDDEN];
__device__ __nv_bfloat16 g_ah[(size_t)T_SEQ * HIDDEN];
__device__ __nv_bfloat16 g_al[(size_t)T_SEQ * HIDDEN];
__device__ __nv_bfloat16 g_wth[4u * HIDDEN * HIDDEN];
__device__ __nv_bfloat16 g_wtl[4u * HIDDEN * HIDDEN];
__device__ __nv_bfloat16 g_qh[(size_t)T_SEQ * HIDDEN];
__device__ __nv_bfloat16 g_ql[(size_t)T_SEQ * HIDDEN];
__device__ __nv_bfloat16 g_kh[(size_t)T_SEQ * HIDDEN];
__device__ __nv_bfloat16 g_kl[(size_t)T_SEQ * HIDDEN];
__device__ __nv_bfloat16 g_vh[(size_t)T_SEQ * HIDDEN];
__device__ __nv_bfloat16 g_vl[(size_t)T_SEQ * HIDDEN];

// ======================= PTX helpers =======================================
__device__ __forceinline__ uint32_t smem_u32(const void* p) {
    uint32_t a;
    asm("{ .reg .u64 t; cvta.to.shared.u64 t, %1; cvt.u32.u64 %0, t; }"
        : "=r"(a) : "l"(p));
    return a;
}
__device__ __forceinline__ void cp_async16(uint32_t s, const void* g) {
    asm volatile("cp.async.cg.shared.global [%0], [%1], 16;" :: "r"(s), "l"(g));
}
#define CP_COMMIT() asm volatile("cp.async.commit_group;" ::: "memory")
#define CP_WAIT1()  asm volatile("cp.async.wait_group 1;" ::: "memory")
#define CP_WAIT0()  asm volatile("cp.async.wait_group 0;" ::: "memory")

__device__ __forceinline__ void ldmx4(uint32_t* r, uint32_t addr) {
    asm volatile("ldmatrix.sync.aligned.m8n8.x4.shared.b16 {%0,%1,%2,%3}, [%4];"
        : "=r"(r[0]), "=r"(r[1]), "=r"(r[2]), "=r"(r[3]) : "r"(addr));
}
__device__ __forceinline__ void ldmx4t(uint32_t* r, uint32_t addr) {
    asm volatile("ldmatrix.sync.aligned.m8n8.x4.trans.shared.b16 {%0,%1,%2,%3}, [%4];"
        : "=r"(r[0]), "=r"(r[1]), "=r"(r[2]), "=r"(r[3]) : "r"(addr));
}
__device__ __forceinline__ void mma_bf16(float* d, const uint32_t* a,
                                         uint32_t b0, uint32_t b1) {
    asm volatile("mma.sync.aligned.m16n8k16.row.col.f32.bf16.bf16.f32 "
        "{%0,%1,%2,%3}, {%4,%5,%6,%7}, {%8,%9}, {%0,%1,%2,%3};"
        : "+f"(d[0]), "+f"(d[1]), "+f"(d[2]), "+f"(d[3])
        : "r"(a[0]), "r"(a[1]), "r"(a[2]), "r"(a[3]), "r"(b0), "r"(b1));
}
__device__ __forceinline__ uint32_t pack_bf16(float lo, float hi) {
    __nv_bfloat162 v;
    v.x = __float2bfloat16(lo);
    v.y = __float2bfloat16(hi);
    return *(uint32_t*)&v;
}
__device__ __forceinline__ uint32_t swz(int row, int cb) {
    return (uint32_t)(row * 256 + (cb ^ ((row & 7) * 16)));
}

// ---------------- split conversions ----------------------------------------
__global__ __launch_bounds__(256) void cvt_split(const float* __restrict__ in,
                                                 __nv_bfloat16* __restrict__ oh,
                                                 __nv_bfloat16* __restrict__ ol) {
    int i = (blockIdx.x * 256 + threadIdx.x) * 4;
    float4 v = *(const float4*)&in[i];
    float x[4] = {v.x, v.y, v.z, v.w};
#pragma unroll
    for (int j = 0; j < 4; j++) {
        __nv_bfloat16 h = __float2bfloat16(x[j]);
        oh[i + j] = h;
        ol[i + j] = __float2bfloat16(x[j] - __bfloat162float(h));
    }
}

__global__ __launch_bounds__(256) void transpose_split(const float* __restrict__ in,
                                                       __nv_bfloat16* __restrict__ oh,
                                                       __nv_bfloat16* __restrict__ ol) {
    __shared__ float t[32][33];
    int x = blockIdx.x * 32 + threadIdx.x;
    int y = blockIdx.y * 32 + threadIdx.y;
#pragma unroll
    for (int j = 0; j < 4; j++)
        t[threadIdx.y + 8 * j][threadIdx.x] = in[(size_t)(y + 8 * j) * HIDDEN + x];
    __syncthreads();
    x = blockIdx.y * 32 + threadIdx.x;
    y = blockIdx.x * 32 + threadIdx.y;
#pragma unroll
    for (int j = 0; j < 4; j++) {
        float v = t[threadIdx.x][threadIdx.y + 8 * j];
        __nv_bfloat16 h = __float2bfloat16(v);
        size_t o = (size_t)(y + 8 * j) * HIDDEN + x;
        oh[o] = h;
        ol[o] = __float2bfloat16(v - __bfloat162float(h));
    }
}

// ---------------- bf16x3 mma.sync GEMM: 2-stage, pass-reordered ------------
#define GS_AH 0
#define GS_AL 10240
#define GS_BH 20480
#define GS_BL 30720
#define GS_STAGE 40960
#define GS_TOTAL (2 * GS_STAGE)
#define G_KCHUNKS (HIDDEN / 32)

__global__ __launch_bounds__(256, 2) void gemm_mma(
    const __nv_bfloat16* __restrict__ Ah, const __nv_bfloat16* __restrict__ Al,
    const __nv_bfloat16* __restrict__ Bh, const __nv_bfloat16* __restrict__ Bl,
    float* __restrict__ C)
{
    extern __shared__ char sm[];
    const uint32_t sb = smem_u32(sm);
    const int tid = threadIdx.x;
    const int lane = tid & 31;
    const int wid = tid >> 5;
    const int wm = wid & 1;
    const int wn = wid >> 1;
    const int bm = blockIdx.y * 128;
    const int bn = blockIdx.x * 128;

    float acc[4][4][4];
#pragma unroll
    for (int a = 0; a < 4; a++)
#pragma unroll
        for (int b = 0; b < 4; b++)
#pragma unroll
            for (int c = 0; c < 4; c++) acc[a][b][c] = 0.f;

    auto issue = [&](int chunk) {
        uint32_t st = sb + (chunk & 1) * GS_STAGE;
        int k0 = chunk * 32;
#pragma unroll
        for (int p = 0; p < 2; p++) {
            int idx = tid + p * 256;
            int row = idx >> 2, c = idx & 3;
            uint32_t soff = row * 80 + c * 16;
            size_t ga = (size_t)(bm + row) * HIDDEN + k0 + c * 8;
            size_t gb = (size_t)(bn + row) * HIDDEN + k0 + c * 8;
            cp_async16(st + GS_AH + soff, Ah + ga);
            cp_async16(st + GS_AL + soff, Al + ga);
            cp_async16(st + GS_BH + soff, Bh + gb);
            cp_async16(st + GS_BL + soff, Bl + gb);
        }
    };

    const uint32_t aBase = (uint32_t)(wm * 64 + (lane & 15)) * 80 + (lane >> 4) * 16;
    const uint32_t bBase = (uint32_t)(wn * 32 + ((lane >> 4) & 1) * 8 + (lane & 7)) * 80
                         + ((lane >> 3) & 1) * 16;

    issue(0); CP_COMMIT();

    for (int i = 0; i < G_KCHUNKS; i++) {
        if (i + 1 < G_KCHUNKS) { issue(i + 1); CP_COMMIT(); CP_WAIT1(); }
        else CP_WAIT0();
        __syncthreads();
        uint32_t st = sb + (i & 1) * GS_STAGE;
#pragma unroll
        for (int kk = 0; kk < 2; kk++) {
            uint32_t aH[4][4], aL[4][4], bH[2][4], bL[2][4];
#pragma unroll
            for (int mt = 0; mt < 4; mt++) {
                ldmx4(aH[mt], st + GS_AH + aBase + mt * 1280 + kk * 32);
                ldmx4(aL[mt], st + GS_AL + aBase + mt * 1280 + kk * 32);
            }
#pragma unroll
            for (int np = 0; np < 2; np++) {
                ldmx4(bH[np], st + GS_BH + bBase + np * 1280 + kk * 32);
                ldmx4(bL[np], st + GS_BL + bBase + np * 1280 + kk * 32);
            }
            // pass-outer: 16 independent accumulators between reuses
#pragma unroll
            for (int pass = 0; pass < 3; pass++)
#pragma unroll
                for (int mt = 0; mt < 4; mt++)
#pragma unroll
                    for (int nt = 0; nt < 4; nt++) {
                        const uint32_t* a = (pass == 1) ? aL[mt] : aH[mt];
                        uint32_t b0, b1;
                        if (pass == 2) {
                            b0 = bL[nt >> 1][(nt & 1) * 2];
                            b1 = bL[nt >> 1][(nt & 1) * 2 + 1];
                        } else {
                            b0 = bH[nt >> 1][(nt & 1) * 2];
                            b1 = bH[nt >> 1][(nt & 1) * 2 + 1];
                        }
                        mma_bf16(acc[mt][nt], a, b0, b1);
                    }
        }
        __syncthreads();
    }

    const int g = lane >> 2, t2 = (lane & 3) * 2;
#pragma unroll
    for (int mt = 0; mt < 4; mt++) {
        int mrow = bm + wm * 64 + mt * 16 + g;
#pragma unroll
        for (int nt = 0; nt < 4; nt++) {
            int ncol = bn + wn * 32 + nt * 8 + t2;
            *(float2*)&C[(size_t)mrow * HIDDEN + ncol] =
                make_float2(acc[mt][nt][0], acc[mt][nt][1]);
            *(float2*)&C[(size_t)(mrow + 8) * HIDDEN + ncol] =
                make_float2(acc[mt][nt][2], acc[mt][nt][3]);
        }
    }
}

// ---------------- fused RoPE + bf16 split for Q,K ---------------------------
__global__ __launch_bounds__(256) void rope_split_qk() {
    int idx = blockIdx.x * blockDim.x + threadIdx.x;
    int d = idx & 63;
    int h = (idx >> 6) & 15;
    int t = (idx >> 10) & (T_SEQ - 1);
    int w = idx >> 22;
    const float* src = g_qkv + (size_t)w * T_SEQ * HIDDEN
                     + (size_t)t * HIDDEN + h * HEAD_DIM;
    __nv_bfloat16* oh = (w == 0 ? g_qh : g_kh) + (size_t)t * HIDDEN + h * HEAD_DIM;
    __nv_bfloat16* ol = (w == 0 ? g_ql : g_kl) + (size_t)t * HIDDEN + h * HEAD_DIM;

    float inv_freq = powf(10000.0f, -(float)d * (1.0f / 64.0f));
    float ang = (float)t * inv_freq;
    float c = cosf(ang), s = sinf(ang);
    float x1 = src[d];
    float x2 = src[d + 64];
    float y1 = x1 * c - x2 * s;
    float y2 = x2 * c + x1 * s;
    __nv_bfloat16 h1 = __float2bfloat16(y1);
    __nv_bfloat16 h2 = __float2bfloat16(y2);
    oh[d] = h1;          ol[d] = __float2bfloat16(y1 - __bfloat162float(h1));
    oh[d + 64] = h2;     ol[d + 64] = __float2bfloat16(y2 - __bfloat162float(h2));
}

// ---------------- flash attention on mma.sync (bf16x3) ---------------------
// 256 threads (8 warps), BQ=128 rows; 64-key tiles, 2-stage cp.async prefetch.
// smem: QH 0 (32KB), QL 32768; KV stage s at 65536 + s*65536:
//       KH +0, KL +16384, VH +32768, VL +49152.  Total 192KB.
#define AT_QH 0
#define AT_QL 32768
#define AT_KV0 65536
#define AT_KVS 65536
#define AT_SMEM 196608

__global__ __launch_bounds__(256, 1) void flash_mma() {
    extern __shared__ char sm[];
    const uint32_t sb = smem_u32(sm);
    const int tid = threadIdx.x;
    const int lane = tid & 31;
    const int w = tid >> 5;
    const int h = blockIdx.y;
    const int qb = (gridDim.x - 1) - blockIdx.x;       // heavy blocks first

    const int g = lane >> 2, t4 = lane & 3;
    const int LAST = 2 * qb + 1;

    const int krow = tid >> 2, kcb = (tid & 3) * 4;

    auto issue_kv = [&](int kb) {
        uint32_t st = sb + AT_KV0 + (kb & 1) * AT_KVS;
        size_t gk = (size_t)(kb * 64 + krow) * HIDDEN + h * HEAD_DIM;
#pragma unroll
        for (int j = 0; j < 4; j++) {
            int c = kcb + j;
            uint32_t off = swz(krow, c * 16);
            cp_async16(st + 0     + off, g_kh + gk + c * 8);
            cp_async16(st + 16384 + off, g_kl + gk + c * 8);
            cp_async16(st + 32768 + off, g_vh + gk + c * 8);
            cp_async16(st + 49152 + off, g_vl + gk + c * 8);
        }
    };

    // ---- Q tile load + first KV tile, one group ----
    {
        int lrow = tid >> 1, cb2 = (tid & 1) * 8;
        size_t gq = (size_t)(qb * 128 + lrow) * HIDDEN + h * HEAD_DIM;
#pragma unroll
        for (int j = 0; j < 8; j++) {
            int c = cb2 + j;
            uint32_t off = swz(lrow, c * 16);
            cp_async16(sb + AT_QH + off, g_qh + gq + c * 8);
            cp_async16(sb + AT_QL + off, g_ql + gq + c * 8);
        }
        issue_kv(0);
        CP_COMMIT();
    }

    float O[16][4];
#pragma unroll
    for (int i = 0; i < 16; i++)
#pragma unroll
        for (int c = 0; c < 4; c++) O[i][c] = 0.f;
    float den0 = 0.f, den1 = 0.f;
    uint32_t qF[8][4];

    const int aRow = w * 16 + (lane & 15);
    const int aHalf = (lane >> 4) * 16;
    const int bRowBase = ((lane >> 4) & 1) * 8 + (lane & 7);
    const int bHalf = ((lane >> 3) & 1) * 16;
    const int vRowBase = ((lane >> 3) & 1) * 8 + (lane & 7);
    const int vHalf = ((lane >> 4) & 1) * 16;

    for (int kb = 0; kb <= LAST; kb++) {
        if (kb + 1 <= LAST) { issue_kv(kb + 1); CP_COMMIT(); CP_WAIT1(); }
        else CP_WAIT0();
        __syncthreads();

        if (kb == 0) {
#pragma unroll
            for (int s = 0; s < 8; s++)
                ldmx4(qF[s], sb + AT_QH + swz(aRow, s * 32 + aHalf));
        }

        const uint32_t st = sb + AT_KV0 + (kb & 1) * AT_KVS;

        // ---- S = Q K^T (bf16x3, pass-reordered) ----
        float S[8][4];
#pragma unroll
        for (int i = 0; i < 8; i++)
#pragma unroll
            for (int c = 0; c < 4; c++) S[i][c] = 0.f;

#pragma unroll
        for (int s = 0; s < 8; s++) {
            uint32_t qlF[4];
            ldmx4(qlF, sb + AT_QL + swz(aRow, s * 32 + aHalf));
            uint32_t bh[4][4], bl[4][4];
#pragma unroll
            for (int p = 0; p < 4; p++) {
                ldmx4(bh[p], st + 0     + swz(bRowBase + p * 16, s * 32 + bHalf));
                ldmx4(bl[p], st + 16384 + swz(bRowBase + p * 16, s * 32 + bHalf));
            }
#pragma unroll
            for (int p = 0; p < 4; p++)
#pragma unroll
                for (int hf = 0; hf < 2; hf++)
                    mma_bf16(S[p * 2 + hf], qF[s], bh[p][hf * 2], bh[p][hf * 2 + 1]);
#pragma unroll
            for (int p = 0; p < 4; p++)
#pragma unroll
                for (int hf = 0; hf < 2; hf++)
                    mma_bf16(S[p * 2 + hf], qlF, bh[p][hf * 2], bh[p][hf * 2 + 1]);
#pragma unroll
            for (int p = 0; p < 4; p++)
#pragma unroll
                for (int hf = 0; hf < 2; hf++)
                    mma_bf16(S[p * 2 + hf], qF[s], bl[p][hf * 2], bl[p][hf * 2 + 1]);
        }

        // ---- softcap + causal + exp ----
        const int rowg = qb * 128 + w * 16 + g;
        const bool diag = (kb >= 2 * qb);
#pragma unroll
        for (int nt = 0; nt < 8; nt++) {
#pragma unroll
            for (int c = 0; c < 4; c++) {
                float a = S[nt][c] * ATT_SCALE;
                float u = a * (2.0f / SOFTCAP);
                float e2 = __expf(u);
                float th = (e2 - 1.0f) / (e2 + 1.0f);
                float p = __expf(th * SOFTCAP);
                if (diag) {
                    int col = kb * 64 + nt * 8 + 2 * t4 + (c & 1);
                    int row = rowg + (c >> 1) * 8;
                    if (col > row) p = 0.f;
                }
                S[nt][c] = p;
                if (c < 2) den0 += p; else den1 += p;
            }
        }

        uint32_t pH[4][4], pL[4][4];
#pragma unroll
        for (int s2 = 0; s2 < 4; s2++) {
            float pf[8] = {S[2*s2][0], S[2*s2][1], S[2*s2][2], S[2*s2][3],
                           S[2*s2+1][0], S[2*s2+1][1], S[2*s2+1][2], S[2*s2+1][3]};
            float lo[8];
#pragma unroll
            for (int e = 0; e < 8; e++) {
                __nv_bfloat16 hb = __float2bfloat16(pf[e]);
                lo[e] = pf[e] - __bfloat162float(hb);
            }
            pH[s2][0] = pack_bf16(pf[0], pf[1]);
            pH[s2][1] = pack_bf16(pf[2], pf[3]);
            pH[s2][2] = pack_bf16(pf[4], pf[5]);
            pH[s2][3] = pack_bf16(pf[6], pf[7]);
            pL[s2][0] = pack_bf16(lo[0], lo[1]);
            pL[s2][1] = pack_bf16(lo[2], lo[3]);
            pL[s2][2] = pack_bf16(lo[4], lo[5]);
            pL[s2][3] = pack_bf16(lo[6], lo[7]);
        }

        // ---- O += P V (bf16x3) ----
#pragma unroll
        for (int s2 = 0; s2 < 4; s2++) {
            int vRow = s2 * 16 + vRowBase;
#pragma unroll
            for (int dp = 0; dp < 8; dp++) {
                uint32_t vh4[4], vl4[4];
                ldmx4t(vh4, st + 32768 + swz(vRow, dp * 32 + vHalf));
                ldmx4t(vl4, st + 49152 + swz(vRow, dp * 32 + vHalf));
#pragma unroll
                for (int hf = 0; hf < 2; hf++)
                    mma_bf16(O[dp * 2 + hf], pH[s2], vh4[hf * 2], vh4[hf * 2 + 1]);
#pragma unroll
                for (int hf = 0; hf < 2; hf++)
                    mma_bf16(O[dp * 2 + hf], pL[s2], vh4[hf * 2], vh4[hf * 2 + 1]);
#pragma unroll
                for (int hf = 0; hf < 2; hf++)
                    mma_bf16(O[dp * 2 + hf], pH[s2], vl4[hf * 2], vl4[hf * 2 + 1]);
            }
        }
        __syncthreads();
    }

    den0 += __shfl_xor_sync(0xFFFFFFFF, den0, 1);
    den0 += __shfl_xor_sync(0xFFFFFFFF, den0, 2);
    den1 += __shfl_xor_sync(0xFFFFFFFF, den1, 1);
    den1 += __shfl_xor_sync(0xFFFFFFFF, den1, 2);
    float inv0 = 1.0f / den0, inv1 = 1.0f / den1;

    const int row0 = qb * 128 + w * 16 + g;
    uint32_t* ahp = (uint32_t*)g_ah;
    uint32_t* alp = (uint32_t*)g_al;
#pragma unroll
    for (int dt = 0; dt < 16; dt++) {
        int col = h * HEAD_DIM + dt * 8 + 2 * t4;
        float v0 = O[dt][0] * inv0, v1 = O[dt][1] * inv0;
        float v2 = O[dt][2] * inv1, v3 = O[dt][3] * inv1;
        __nv_bfloat16 h0 = __float2bfloat16(v0), h1v = __float2bfloat16(v1);
        __nv_bfloat16 h2 = __float2bfloat16(v2), h3 = __float2bfloat16(v3);
        size_t o0 = ((size_t)row0 * HIDDEN + col) >> 1;
        size_t o1 = ((size_t)(row0 + 8) * HIDDEN + col) >> 1;
        ahp[o0] = pack_bf16(__bfloat162float(h0), __bfloat162float(h1v));
        alp[o0] = pack_bf16(v0 - __bfloat162float(h0), v1 - __bfloat162float(h1v));
        ahp[o1] = pack_bf16(__bfloat162float(h2), __bfloat162float(h3));
        alp[o1] = pack_bf16(v2 - __bfloat162float(h2), v3 - __bfloat162float(h3));
    }
}

// ---------------- launch ----------------------------------------------------
extern "C" void kernel_launch(void* const* d_in, const int* in_sizes, int n_in,
                              void* d_out, int out_size) {
    const float* X  = (const float*)d_in[0];
    const float* Wq = (const float*)d_in[1];
    const float* Wk = (const float*)d_in[2];
    const float* Wv = (const float*)d_in[3];
    const float* Wo = (const float*)d_in[4];
    float* out = (float*)d_out;

    float* qkv; cudaGetSymbolAddress((void**)&qkv, g_qkv);
    __nv_bfloat16 *xh, *xl, *ah, *al, *wth, *wtl, *vh, *vl;
    cudaGetSymbolAddress((void**)&xh, g_xh);
    cudaGetSymbolAddress((void**)&xl, g_xl);
    cudaGetSymbolAddress((void**)&ah, g_ah);
    cudaGetSymbolAddress((void**)&al, g_al);
    cudaGetSymbolAddress((void**)&wth, g_wth);
    cudaGetSymbolAddress((void**)&wtl, g_wtl);
    cudaGetSymbolAddress((void**)&vh, g_vh);
    cudaGetSymbolAddress((void**)&vl, g_vl);

    float* q = qkv;
    float* k = qkv + (size_t)T_SEQ * HIDDEN;
    float* v = qkv + 2u * T_SEQ * HIDDEN;

    cudaFuncSetAttribute(gemm_mma, cudaFuncAttributeMaxDynamicSharedMemorySize, GS_TOTAL);
    cudaFuncSetAttribute(flash_mma, cudaFuncAttributeMaxDynamicSharedMemorySize, AT_SMEM);

    const size_t WSTRIDE = (size_t)HIDDEN * HIDDEN;
    dim3 tb(32, 8);
    dim3 tg(HIDDEN / 32, HIDDEN / 32);
    transpose_split<<<tg, tb>>>(Wq, wth + 0 * WSTRIDE, wtl + 0 * WSTRIDE);
    transpose_split<<<tg, tb>>>(Wk, wth + 1 * WSTRIDE, wtl + 1 * WSTRIDE);
    transpose_split<<<tg, tb>>>(Wv, wth + 2 * WSTRIDE, wtl + 2 * WSTRIDE);
    transpose_split<<<tg, tb>>>(Wo, wth + 3 * WSTRIDE, wtl + 3 * WSTRIDE);

    cvt_split<<<(T_SEQ * HIDDEN) / 1024, 256>>>(X, xh, xl);

    dim3 gg(HIDDEN / 128, T_SEQ / 128);
    gemm_mma<<<gg, 256, GS_TOTAL>>>(xh, xl, wth + 0 * WSTRIDE, wtl + 0 * WSTRIDE, q);
    gemm_mma<<<gg, 256, GS_TOTAL>>>(xh, xl, wth + 1 * WSTRIDE, wtl + 1 * WSTRIDE, k);
    gemm_mma<<<gg, 256, GS_TOTAL>>>(xh, xl, wth + 2 * WSTRIDE, wtl + 2 * WSTRIDE, v);

    rope_split_qk<<<8388608 / 256, 256>>>();
    cvt_split<<<(T_SEQ * HIDDEN) / 1024, 256>>>(v, vh, vl);

    flash_mma<<<dim3(T_SEQ / 128, NHEADS), 256, AT_SMEM>>>();

    gemm_mma<<<gg, 256, GS_TOTAL>>>(ah, al, wth + 3 * WSTRIDE, wtl + 3 * WSTRIDE, out);
}

// round 7
// speedup vs baseline: 4.9288x; 1.4528x over previous
#include <cuda_runtime.h>
#include <cuda_fp16.h>
#include <cstdint>
#include <math.h>

#define T_SEQ 4096
#define HIDDEN 2048
#define NHEADS 16
#define HEAD_DIM 128
#define SOFTCAP 50.0f
#define ATT_SCALE 0.0625f   // 256^-0.5

// ---------------- scratch (device globals; allocation-free) ----------------
__device__ float g_qkv[3u * T_SEQ * HIDDEN];
__device__ __half g_xh[(size_t)T_SEQ * HIDDEN];
__device__ __half g_xl[(size_t)T_SEQ * HIDDEN];
__device__ __half g_ah[(size_t)T_SEQ * HIDDEN];   // attention out hi
__device__ __half g_al[(size_t)T_SEQ * HIDDEN];   // attention out lo
__device__ __half g_wth[4u * HIDDEN * HIDDEN];    // transposed weights (fp16, hi only)
__device__ __half g_qh[(size_t)T_SEQ * HIDDEN];
__device__ __half g_ql[(size_t)T_SEQ * HIDDEN];
__device__ __half g_kh[(size_t)T_SEQ * HIDDEN];   // K single fp16 (B side)
__device__ __half g_vh[(size_t)T_SEQ * HIDDEN];   // V single fp16 (B side)

// ======================= PTX helpers =======================================
__device__ __forceinline__ uint32_t smem_u32(const void* p) {
    uint32_t a;
    asm("{ .reg .u64 t; cvta.to.shared.u64 t, %1; cvt.u32.u64 %0, t; }"
        : "=r"(a) : "l"(p));
    return a;
}
__device__ __forceinline__ void cp_async16(uint32_t s, const void* g) {
    asm volatile("cp.async.cg.shared.global [%0], [%1], 16;" :: "r"(s), "l"(g));
}
#define CP_COMMIT() asm volatile("cp.async.commit_group;" ::: "memory")
#define CP_WAIT1()  asm volatile("cp.async.wait_group 1;" ::: "memory")
#define CP_WAIT0()  asm volatile("cp.async.wait_group 0;" ::: "memory")

__device__ __forceinline__ void ldmx4(uint32_t* r, uint32_t addr) {
    asm volatile("ldmatrix.sync.aligned.m8n8.x4.shared.b16 {%0,%1,%2,%3}, [%4];"
        : "=r"(r[0]), "=r"(r[1]), "=r"(r[2]), "=r"(r[3]) : "r"(addr));
}
__device__ __forceinline__ void ldmx4t(uint32_t* r, uint32_t addr) {
    asm volatile("ldmatrix.sync.aligned.m8n8.x4.trans.shared.b16 {%0,%1,%2,%3}, [%4];"
        : "=r"(r[0]), "=r"(r[1]), "=r"(r[2]), "=r"(r[3]) : "r"(addr));
}
__device__ __forceinline__ void mma_f16(float* d, const uint32_t* a,
                                        uint32_t b0, uint32_t b1) {
    asm volatile("mma.sync.aligned.m16n8k16.row.col.f32.f16.f16.f32 "
        "{%0,%1,%2,%3}, {%4,%5,%6,%7}, {%8,%9}, {%0,%1,%2,%3};"
        : "+f"(d[0]), "+f"(d[1]), "+f"(d[2]), "+f"(d[3])
        : "r"(a[0]), "r"(a[1]), "r"(a[2]), "r"(a[3]), "r"(b0), "r"(b1));
}
__device__ __forceinline__ uint32_t pack_h2(float lo, float hi) {
    __half2 v;
    v.x = __float2half(lo);
    v.y = __float2half(hi);
    return *(uint32_t*)&v;
}
__device__ __forceinline__ uint32_t swz(int row, int cb) {
    return (uint32_t)(row * 256 + (cb ^ ((row & 7) * 16)));
}

// ---------------- conversions ----------------------------------------------
__global__ __launch_bounds__(256) void cvt_split(const float* __restrict__ in,
                                                 __half* __restrict__ oh,
                                                 __half* __restrict__ ol) {
    int i = (blockIdx.x * 256 + threadIdx.x) * 4;
    float4 v = *(const float4*)&in[i];
    float x[4] = {v.x, v.y, v.z, v.w};
#pragma unroll
    for (int j = 0; j < 4; j++) {
        __half h = __float2half(x[j]);
        oh[i + j] = h;
        ol[i + j] = __float2half(x[j] - __half2float(h));
    }
}

__global__ __launch_bounds__(256) void cvt_half(const float* __restrict__ in,
                                                __half* __restrict__ oh) {
    int i = (blockIdx.x * 256 + threadIdx.x) * 4;
    float4 v = *(const float4*)&in[i];
    oh[i + 0] = __float2half(v.x);
    oh[i + 1] = __float2half(v.y);
    oh[i + 2] = __float2half(v.z);
    oh[i + 3] = __float2half(v.w);
}

// fused 4-way transpose 2048x2048 fp32 -> fp16 at [n][k]; z selects matrix
__global__ __launch_bounds__(256) void transpose_half4(
    const float* __restrict__ w0, const float* __restrict__ w1,
    const float* __restrict__ w2, const float* __restrict__ w3,
    __half* __restrict__ out)
{
    __shared__ float t[32][33];
    const float* in = (blockIdx.z == 0) ? w0 : (blockIdx.z == 1) ? w1
                    : (blockIdx.z == 2) ? w2 : w3;
    __half* o = out + (size_t)blockIdx.z * HIDDEN * HIDDEN;
    int x = blockIdx.x * 32 + threadIdx.x;
    int y = blockIdx.y * 32 + threadIdx.y;
#pragma unroll
    for (int j = 0; j < 4; j++)
        t[threadIdx.y + 8 * j][threadIdx.x] = in[(size_t)(y + 8 * j) * HIDDEN + x];
    __syncthreads();
    x = blockIdx.y * 32 + threadIdx.x;
    y = blockIdx.x * 32 + threadIdx.y;
#pragma unroll
    for (int j = 0; j < 4; j++)
        o[(size_t)(y + 8 * j) * HIDDEN + x] = __float2half(t[threadIdx.x][threadIdx.y + 8 * j]);
}

// ---------------- fp16 A-split 2-pass mma GEMM ------------------------------
// C[z][4096,2048] = (Ah+Al) @ B[z]^T;  B fp16 hi only.
// Tile 128x128, BK=32, 2-stage cp.async; 8 warps (2m x 4n).
// smem/stage: AH 0(10KB), AL 10240, BH 20480 -> 30720B; 2 stages = 61440B.
#define GS_AH 0
#define GS_AL 10240
#define GS_BH 20480
#define GS_STAGE 30720
#define GS_TOTAL (2 * GS_STAGE)
#define G_KCHUNKS (HIDDEN / 32)

__global__ __launch_bounds__(256, 2) void gemm_mma(
    const __half* __restrict__ Ah, const __half* __restrict__ Al,
    const __half* __restrict__ B0, float* __restrict__ C0,
    size_t bStrideZ, size_t cStrideZ)
{
    extern __shared__ char sm[];
    const uint32_t sb = smem_u32(sm);
    const int tid = threadIdx.x;
    const int lane = tid & 31;
    const int wid = tid >> 5;
    const int wm = wid & 1;
    const int wn = wid >> 1;
    const int bm = blockIdx.y * 128;
    const int bn = blockIdx.x * 128;
    const __half* B = B0 + (size_t)blockIdx.z * bStrideZ;
    float* C = C0 + (size_t)blockIdx.z * cStrideZ;

    float acc[4][4][4];
#pragma unroll
    for (int a = 0; a < 4; a++)
#pragma unroll
        for (int b = 0; b < 4; b++)
#pragma unroll
            for (int c = 0; c < 4; c++) acc[a][b][c] = 0.f;

    auto issue = [&](int chunk) {
        uint32_t st = sb + (chunk & 1) * GS_STAGE;
        int k0 = chunk * 32;
#pragma unroll
        for (int p = 0; p < 2; p++) {
            int idx = tid + p * 256;
            int row = idx >> 2, c = idx & 3;
            uint32_t soff = row * 80 + c * 16;
            size_t ga = (size_t)(bm + row) * HIDDEN + k0 + c * 8;
            size_t gb = (size_t)(bn + row) * HIDDEN + k0 + c * 8;
            cp_async16(st + GS_AH + soff, Ah + ga);
            cp_async16(st + GS_AL + soff, Al + ga);
            cp_async16(st + GS_BH + soff, B + gb);
        }
    };

    const uint32_t aBase = (uint32_t)(wm * 64 + (lane & 15)) * 80 + (lane >> 4) * 16;
    const uint32_t bBase = (uint32_t)(wn * 32 + ((lane >> 4) & 1) * 8 + (lane & 7)) * 80
                         + ((lane >> 3) & 1) * 16;

    issue(0); CP_COMMIT();

    for (int i = 0; i < G_KCHUNKS; i++) {
        if (i + 1 < G_KCHUNKS) { issue(i + 1); CP_COMMIT(); CP_WAIT1(); }
        else CP_WAIT0();
        __syncthreads();
        uint32_t st = sb + (i & 1) * GS_STAGE;
#pragma unroll
        for (int kk = 0; kk < 2; kk++) {
            uint32_t aH[4][4], aL[4][4], bH[2][4];
#pragma unroll
            for (int mt = 0; mt < 4; mt++) {
                ldmx4(aH[mt], st + GS_AH + aBase + mt * 1280 + kk * 32);
                ldmx4(aL[mt], st + GS_AL + aBase + mt * 1280 + kk * 32);
            }
#pragma unroll
            for (int np = 0; np < 2; np++)
                ldmx4(bH[np], st + GS_BH + bBase + np * 1280 + kk * 32);
#pragma unroll
            for (int pass = 0; pass < 2; pass++)
#pragma unroll
                for (int mt = 0; mt < 4; mt++)
#pragma unroll
                    for (int nt = 0; nt < 4; nt++) {
                        const uint32_t* a = pass ? aL[mt] : aH[mt];
                        mma_f16(acc[mt][nt], a,
                                bH[nt >> 1][(nt & 1) * 2],
                                bH[nt >> 1][(nt & 1) * 2 + 1]);
                    }
        }
        __syncthreads();
    }

    const int g = lane >> 2, t2 = (lane & 3) * 2;
#pragma unroll
    for (int mt = 0; mt < 4; mt++) {
        int mrow = bm + wm * 64 + mt * 16 + g;
#pragma unroll
        for (int nt = 0; nt < 4; nt++) {
            int ncol = bn + wn * 32 + nt * 8 + t2;
            *(float2*)&C[(size_t)mrow * HIDDEN + ncol] =
                make_float2(acc[mt][nt][0], acc[mt][nt][1]);
            *(float2*)&C[(size_t)(mrow + 8) * HIDDEN + ncol] =
                make_float2(acc[mt][nt][2], acc[mt][nt][3]);
        }
    }
}

// ---------------- fused RoPE + fp16 split (Q) / fp16 (K) -------------------
__global__ __launch_bounds__(256) void rope_split_qk() {
    int idx = blockIdx.x * blockDim.x + threadIdx.x;
    int d = idx & 63;
    int h = (idx >> 6) & 15;
    int t = (idx >> 10) & (T_SEQ - 1);
    int w = idx >> 22;                                  // 0=q, 1=k
    const float* src = g_qkv + (size_t)w * T_SEQ * HIDDEN
                     + (size_t)t * HIDDEN + h * HEAD_DIM;

    float inv_freq = powf(10000.0f, -(float)d * (1.0f / 64.0f));
    float ang = (float)t * inv_freq;
    float c = cosf(ang), s = sinf(ang);
    float x1 = src[d];
    float x2 = src[d + 64];
    float y1 = x1 * c - x2 * s;
    float y2 = x2 * c + x1 * s;

    size_t o = (size_t)t * HIDDEN + h * HEAD_DIM;
    if (w == 0) {
        __half h1 = __float2half(y1);
        __half h2 = __float2half(y2);
        g_qh[o + d] = h1;       g_ql[o + d] = __float2half(y1 - __half2float(h1));
        g_qh[o + d + 64] = h2;  g_ql[o + d + 64] = __float2half(y2 - __half2float(h2));
    } else {
        g_kh[o + d] = __float2half(y1);
        g_kh[o + d + 64] = __float2half(y2);
    }
}

// ---------------- flash attention, fp16 A-split 2-pass ----------------------
// 256 threads (8 warps), BQ=128; 64-key tiles, 2-stage KV prefetch.
// smem: QH 0 (32KB), QL 32768 (32KB); KV stage s at 65536 + s*32768:
//       KH +0 (16KB), VH +16384 (16KB).  Total 128KB.
#define AT_QH 0
#define AT_QL 32768
#define AT_KV0 65536
#define AT_KVS 32768
#define AT_SMEM 131072

__global__ __launch_bounds__(256, 1) void flash_mma() {
    extern __shared__ char sm[];
    const uint32_t sb = smem_u32(sm);
    const int tid = threadIdx.x;
    const int lane = tid & 31;
    const int w = tid >> 5;
    const int h = blockIdx.y;
    const int qb = (gridDim.x - 1) - blockIdx.x;       // heavy blocks first

    const int g = lane >> 2, t4 = lane & 3;
    const int LAST = 2 * qb + 1;

    const int krow = tid >> 2, kcb = (tid & 3) * 4;

    auto issue_kv = [&](int kb) {
        uint32_t st = sb + AT_KV0 + (kb & 1) * AT_KVS;
        size_t gk = (size_t)(kb * 64 + krow) * HIDDEN + h * HEAD_DIM;
#pragma unroll
        for (int j = 0; j < 4; j++) {
            int c = kcb + j;
            uint32_t off = swz(krow, c * 16);
            cp_async16(st + 0     + off, g_kh + gk + c * 8);
            cp_async16(st + 16384 + off, g_vh + gk + c * 8);
        }
    };

    {
        int lrow = tid >> 1, cb2 = (tid & 1) * 8;
        size_t gq = (size_t)(qb * 128 + lrow) * HIDDEN + h * HEAD_DIM;
#pragma unroll
        for (int j = 0; j < 8; j++) {
            int c = cb2 + j;
            uint32_t off = swz(lrow, c * 16);
            cp_async16(sb + AT_QH + off, g_qh + gq + c * 8);
            cp_async16(sb + AT_QL + off, g_ql + gq + c * 8);
        }
        issue_kv(0);
        CP_COMMIT();
    }

    float O[16][4];
#pragma unroll
    for (int i = 0; i < 16; i++)
#pragma unroll
        for (int c = 0; c < 4; c++) O[i][c] = 0.f;
    float den0 = 0.f, den1 = 0.f;
    uint32_t qF[8][4], qlF[8][4];

    const int aRow = w * 16 + (lane & 15);
    const int aHalf = (lane >> 4) * 16;
    const int bRowBase = ((lane >> 4) & 1) * 8 + (lane & 7);
    const int bHalf = ((lane >> 3) & 1) * 16;
    const int vRowBase = ((lane >> 3) & 1) * 8 + (lane & 7);
    const int vHalf = ((lane >> 4) & 1) * 16;

    for (int kb = 0; kb <= LAST; kb++) {
        if (kb + 1 <= LAST) { issue_kv(kb + 1); CP_COMMIT(); CP_WAIT1(); }
        else CP_WAIT0();
        __syncthreads();

        if (kb == 0) {
#pragma unroll
            for (int s = 0; s < 8; s++) {
                ldmx4(qF[s],  sb + AT_QH + swz(aRow, s * 32 + aHalf));
                ldmx4(qlF[s], sb + AT_QL + swz(aRow, s * 32 + aHalf));
            }
        }

        const uint32_t st = sb + AT_KV0 + (kb & 1) * AT_KVS;

        // ---- S = Q K^T (fp16 2-pass) ----
        float S[8][4];
#pragma unroll
        for (int i = 0; i < 8; i++)
#pragma unroll
            for (int c = 0; c < 4; c++) S[i][c] = 0.f;

#pragma unroll
        for (int s = 0; s < 8; s++) {
            uint32_t bh[4][4];
#pragma unroll
            for (int p = 0; p < 4; p++)
                ldmx4(bh[p], st + swz(bRowBase + p * 16, s * 32 + bHalf));
#pragma unroll
            for (int p = 0; p < 4; p++)
#pragma unroll
                for (int hf = 0; hf < 2; hf++)
                    mma_f16(S[p * 2 + hf], qF[s], bh[p][hf * 2], bh[p][hf * 2 + 1]);
#pragma unroll
            for (int p = 0; p < 4; p++)
#pragma unroll
                for (int hf = 0; hf < 2; hf++)
                    mma_f16(S[p * 2 + hf], qlF[s], bh[p][hf * 2], bh[p][hf * 2 + 1]);
        }

        // ---- softcap + causal + exp ----
        const int rowg = qb * 128 + w * 16 + g;
        const bool diag = (kb >= 2 * qb);
#pragma unroll
        for (int nt = 0; nt < 8; nt++) {
#pragma unroll
            for (int c = 0; c < 4; c++) {
                float a = S[nt][c] * ATT_SCALE;
                float u = a * (2.0f / SOFTCAP);
                float e2 = __expf(u);
                float th = (e2 - 1.0f) / (e2 + 1.0f);
                float p = __expf(th * SOFTCAP);
                if (diag) {
                    int col = kb * 64 + nt * 8 + 2 * t4 + (c & 1);
                    int row = rowg + (c >> 1) * 8;
                    if (col > row) p = 0.f;
                }
                S[nt][c] = p;
                if (c < 2) den0 += p; else den1 += p;
            }
        }

        uint32_t pH[4][4], pL[4][4];
#pragma unroll
        for (int s2 = 0; s2 < 4; s2++) {
            float pf[8] = {S[2*s2][0], S[2*s2][1], S[2*s2][2], S[2*s2][3],
                           S[2*s2+1][0], S[2*s2+1][1], S[2*s2+1][2], S[2*s2+1][3]};
            float lo[8];
#pragma unroll
            for (int e = 0; e < 8; e++) {
                __half hb = __float2half(pf[e]);
                lo[e] = pf[e] - __half2float(hb);
            }
            pH[s2][0] = pack_h2(pf[0], pf[1]);
            pH[s2][1] = pack_h2(pf[2], pf[3]);
            pH[s2][2] = pack_h2(pf[4], pf[5]);
            pH[s2][3] = pack_h2(pf[6], pf[7]);
            pL[s2][0] = pack_h2(lo[0], lo[1]);
            pL[s2][1] = pack_h2(lo[2], lo[3]);
            pL[s2][2] = pack_h2(lo[4], lo[5]);
            pL[s2][3] = pack_h2(lo[6], lo[7]);
        }

        // ---- O += P V (fp16 2-pass) ----
#pragma unroll
        for (int s2 = 0; s2 < 4; s2++) {
            int vRow = s2 * 16 + vRowBase;
#pragma unroll
            for (int dp = 0; dp < 8; dp++) {
                uint32_t vh4[4];
                ldmx4t(vh4, st + 16384 + swz(vRow, dp * 32 + vHalf));
#pragma unroll
                for (int hf = 0; hf < 2; hf++)
                    mma_f16(O[dp * 2 + hf], pH[s2], vh4[hf * 2], vh4[hf * 2 + 1]);
#pragma unroll
                for (int hf = 0; hf < 2; hf++)
                    mma_f16(O[dp * 2 + hf], pL[s2], vh4[hf * 2], vh4[hf * 2 + 1]);
            }
        }
        __syncthreads();
    }

    den0 += __shfl_xor_sync(0xFFFFFFFF, den0, 1);
    den0 += __shfl_xor_sync(0xFFFFFFFF, den0, 2);
    den1 += __shfl_xor_sync(0xFFFFFFFF, den1, 1);
    den1 += __shfl_xor_sync(0xFFFFFFFF, den1, 2);
    float inv0 = 1.0f / den0, inv1 = 1.0f / den1;

    const int row0 = qb * 128 + w * 16 + g;
    uint32_t* ahp = (uint32_t*)g_ah;
    uint32_t* alp = (uint32_t*)g_al;
#pragma unroll
    for (int dt = 0; dt < 16; dt++) {
        int col = h * HEAD_DIM + dt * 8 + 2 * t4;
        float v0 = O[dt][0] * inv0, v1 = O[dt][1] * inv0;
        float v2 = O[dt][2] * inv1, v3 = O[dt][3] * inv1;
        __half h0 = __float2half(v0), h1v = __float2half(v1);
        __half h2 = __float2half(v2), h3 = __float2half(v3);
        size_t o0 = ((size_t)row0 * HIDDEN + col) >> 1;
        size_t o1 = ((size_t)(row0 + 8) * HIDDEN + col) >> 1;
        ahp[o0] = pack_h2(__half2float(h0), __half2float(h1v));
        alp[o0] = pack_h2(v0 - __half2float(h0), v1 - __half2float(h1v));
        ahp[o1] = pack_h2(__half2float(h2), __half2float(h3));
        alp[o1] = pack_h2(v2 - __half2float(h2), v3 - __half2float(h3));
    }
}

// ---------------- launch ----------------------------------------------------
extern "C" void kernel_launch(void* const* d_in, const int* in_sizes, int n_in,
                              void* d_out, int out_size) {
    const float* X  = (const float*)d_in[0];
    const float* Wq = (const float*)d_in[1];
    const float* Wk = (const float*)d_in[2];
    const float* Wv = (const float*)d_in[3];
    const float* Wo = (const float*)d_in[4];
    float* out = (float*)d_out;

    float* qkv; cudaGetSymbolAddress((void**)&qkv, g_qkv);
    __half *xh, *xl, *ah, *al, *wth, *vh;
    cudaGetSymbolAddress((void**)&xh, g_xh);
    cudaGetSymbolAddress((void**)&xl, g_xl);
    cudaGetSymbolAddress((void**)&ah, g_ah);
    cudaGetSymbolAddress((void**)&al, g_al);
    cudaGetSymbolAddress((void**)&wth, g_wth);
    cudaGetSymbolAddress((void**)&vh, g_vh);

    float* v = qkv + 2u * T_SEQ * HIDDEN;

    cudaFuncSetAttribute(gemm_mma, cudaFuncAttributeMaxDynamicSharedMemorySize, GS_TOTAL);
    cudaFuncSetAttribute(flash_mma, cudaFuncAttributeMaxDynamicSharedMemorySize, AT_SMEM);

    const size_t WSTRIDE = (size_t)HIDDEN * HIDDEN;

    transpose_half4<<<dim3(HIDDEN / 32, HIDDEN / 32, 4), dim3(32, 8)>>>(Wq, Wk, Wv, Wo, wth);
    cvt_split<<<(T_SEQ * HIDDEN) / 1024, 256>>>(X, xh, xl);

    // fused QKV: z selects weight & output
    gemm_mma<<<dim3(HIDDEN / 128, T_SEQ / 128, 3), 256, GS_TOTAL>>>(
        xh, xl, wth, qkv, WSTRIDE, (size_t)T_SEQ * HIDDEN);

    rope_split_qk<<<8388608 / 256, 256>>>();
    cvt_half<<<(T_SEQ * HIDDEN) / 1024, 256>>>(v, vh);

    flash_mma<<<dim3(T_SEQ / 128, NHEADS), 256, AT_SMEM>>>();

    gemm_mma<<<dim3(HIDDEN / 128, T_SEQ / 128, 1), 256, GS_TOTAL>>>(
        ah, al, wth + 3 * WSTRIDE, out, 0, 0);
}

// round 9
// speedup vs baseline: 6.8340x; 1.3866x over previous
#include <cuda_runtime.h>
#include <cuda_fp16.h>
#include <cstdint>
#include <math.h>

#define T_SEQ 4096
#define HIDDEN 2048
#define NHEADS 16
#define HEAD_DIM 128
#define SOFTCAP 50.0f
#define ATT_SCALE 0.0625f   // 256^-0.5

// ---------------- scratch (device globals; allocation-free) ----------------
__device__ float g_qkv[3u * T_SEQ * HIDDEN];
__device__ __half g_xh[(size_t)T_SEQ * HIDDEN];
__device__ __half g_ah[(size_t)T_SEQ * HIDDEN];   // attention out (fp16)
__device__ __half g_wth[4u * HIDDEN * HIDDEN];    // transposed weights (fp16)
__device__ __half g_qh[(size_t)T_SEQ * HIDDEN];
__device__ __half g_kh[(size_t)T_SEQ * HIDDEN];
__device__ __half g_vh[(size_t)T_SEQ * HIDDEN];

// ======================= PTX helpers =======================================
__device__ __forceinline__ uint32_t smem_u32(const void* p) {
    uint32_t a;
    asm("{ .reg .u64 t; cvta.to.shared.u64 t, %1; cvt.u32.u64 %0, t; }"
        : "=r"(a) : "l"(p));
    return a;
}
__device__ __forceinline__ void cp_async16(uint32_t s, const void* g) {
    asm volatile("cp.async.cg.shared.global [%0], [%1], 16;" :: "r"(s), "l"(g));
}
#define CP_COMMIT() asm volatile("cp.async.commit_group;" ::: "memory")
#define CP_WAIT1()  asm volatile("cp.async.wait_group 1;" ::: "memory")
#define CP_WAIT0()  asm volatile("cp.async.wait_group 0;" ::: "memory")

__device__ __forceinline__ void ldmx4(uint32_t* r, uint32_t addr) {
    asm volatile("ldmatrix.sync.aligned.m8n8.x4.shared.b16 {%0,%1,%2,%3}, [%4];"
        : "=r"(r[0]), "=r"(r[1]), "=r"(r[2]), "=r"(r[3]) : "r"(addr));
}
__device__ __forceinline__ void ldmx4t(uint32_t* r, uint32_t addr) {
    asm volatile("ldmatrix.sync.aligned.m8n8.x4.trans.shared.b16 {%0,%1,%2,%3}, [%4];"
        : "=r"(r[0]), "=r"(r[1]), "=r"(r[2]), "=r"(r[3]) : "r"(addr));
}
__device__ __forceinline__ void mma_f16(float* d, const uint32_t* a,
                                        uint32_t b0, uint32_t b1) {
    asm volatile("mma.sync.aligned.m16n8k16.row.col.f32.f16.f16.f32 "
        "{%0,%1,%2,%3}, {%4,%5,%6,%7}, {%8,%9}, {%0,%1,%2,%3};"
        : "+f"(d[0]), "+f"(d[1]), "+f"(d[2]), "+f"(d[3])
        : "r"(a[0]), "r"(a[1]), "r"(a[2]), "r"(a[3]), "r"(b0), "r"(b1));
}
__device__ __forceinline__ uint32_t pack_h2(float lo, float hi) {
    __half2 v;
    v.x = __float2half(lo);
    v.y = __float2half(hi);
    return *(uint32_t*)&v;
}
__device__ __forceinline__ uint32_t swz(int row, int cb) {
    return (uint32_t)(row * 256 + (cb ^ ((row & 7) * 16)));
}

// ---------------- conversions ----------------------------------------------
__global__ __launch_bounds__(256) void cvt_half(const float* __restrict__ in,
                                                __half* __restrict__ oh) {
    int i = (blockIdx.x * 256 + threadIdx.x) * 4;
    float4 v = *(const float4*)&in[i];
    oh[i + 0] = __float2half(v.x);
    oh[i + 1] = __float2half(v.y);
    oh[i + 2] = __float2half(v.z);
    oh[i + 3] = __float2half(v.w);
}

// fused 4-way transpose 2048x2048 fp32 -> fp16 at [n][k]; z selects matrix
__global__ __launch_bounds__(256) void transpose_half4(
    const float* __restrict__ w0, const float* __restrict__ w1,
    const float* __restrict__ w2, const float* __restrict__ w3,
    __half* __restrict__ out)
{
    __shared__ float t[32][33];
    const float* in = (blockIdx.z == 0) ? w0 : (blockIdx.z == 1) ? w1
                    : (blockIdx.z == 2) ? w2 : w3;
    __half* o = out + (size_t)blockIdx.z * HIDDEN * HIDDEN;
    int x = blockIdx.x * 32 + threadIdx.x;
    int y = blockIdx.y * 32 + threadIdx.y;
#pragma unroll
    for (int j = 0; j < 4; j++)
        t[threadIdx.y + 8 * j][threadIdx.x] = in[(size_t)(y + 8 * j) * HIDDEN + x];
    __syncthreads();
    x = blockIdx.y * 32 + threadIdx.x;
    y = blockIdx.x * 32 + threadIdx.y;
#pragma unroll
    for (int j = 0; j < 4; j++)
        o[(size_t)(y + 8 * j) * HIDDEN + x] = __float2half(t[threadIdx.x][threadIdx.y + 8 * j]);
}

// ---------------- fp16 single-pass mma GEMM --------------------------------
// C[z][4096,2048] = A @ B[z]^T, both single fp16.
// Tile 128x128, BK=32, 2-stage cp.async; 8 warps (2m x 4n).
// smem/stage: AH 0 (10KB), BH 10240 -> 20480B; 2 stages = 40960B.
#define GS_AH 0
#define GS_BH 10240
#define GS_STAGE 20480
#define GS_TOTAL (2 * GS_STAGE)
#define G_KCHUNKS (HIDDEN / 32)

__global__ __launch_bounds__(256, 2) void gemm_mma(
    const __half* __restrict__ Ah,
    const __half* __restrict__ B0, float* __restrict__ C0,
    size_t bStrideZ, size_t cStrideZ)
{
    extern __shared__ char sm[];
    const uint32_t sb = smem_u32(sm);
    const int tid = threadIdx.x;
    const int lane = tid & 31;
    const int wid = tid >> 5;
    const int wm = wid & 1;
    const int wn = wid >> 1;
    const int bm = blockIdx.y * 128;
    const int bn = blockIdx.x * 128;
    const __half* B = B0 + (size_t)blockIdx.z * bStrideZ;
    float* C = C0 + (size_t)blockIdx.z * cStrideZ;

    float acc[4][4][4];
#pragma unroll
    for (int a = 0; a < 4; a++)
#pragma unroll
        for (int b = 0; b < 4; b++)
#pragma unroll
            for (int c = 0; c < 4; c++) acc[a][b][c] = 0.f;

    auto issue = [&](int chunk) {
        uint32_t st = sb + (chunk & 1) * GS_STAGE;
        int k0 = chunk * 32;
#pragma unroll
        for (int p = 0; p < 2; p++) {
            int idx = tid + p * 256;
            int row = idx >> 2, c = idx & 3;
            uint32_t soff = row * 80 + c * 16;
            size_t ga = (size_t)(bm + row) * HIDDEN + k0 + c * 8;
            size_t gb = (size_t)(bn + row) * HIDDEN + k0 + c * 8;
            cp_async16(st + GS_AH + soff, Ah + ga);
            cp_async16(st + GS_BH + soff, B + gb);
        }
    };

    const uint32_t aBase = (uint32_t)(wm * 64 + (lane & 15)) * 80 + (lane >> 4) * 16;
    const uint32_t bBase = (uint32_t)(wn * 32 + ((lane >> 4) & 1) * 8 + (lane & 7)) * 80
                         + ((lane >> 3) & 1) * 16;

    issue(0); CP_COMMIT();

    for (int i = 0; i < G_KCHUNKS; i++) {
        if (i + 1 < G_KCHUNKS) { issue(i + 1); CP_COMMIT(); CP_WAIT1(); }
        else CP_WAIT0();
        __syncthreads();
        uint32_t st = sb + (i & 1) * GS_STAGE;
#pragma unroll
        for (int kk = 0; kk < 2; kk++) {
            uint32_t aH[4][4], bH[2][4];
#pragma unroll
            for (int mt = 0; mt < 4; mt++)
                ldmx4(aH[mt], st + GS_AH + aBase + mt * 1280 + kk * 32);
#pragma unroll
            for (int np = 0; np < 2; np++)
                ldmx4(bH[np], st + GS_BH + bBase + np * 1280 + kk * 32);
#pragma unroll
            for (int mt = 0; mt < 4; mt++)
#pragma unroll
                for (int nt = 0; nt < 4; nt++)
                    mma_f16(acc[mt][nt], aH[mt],
                            bH[nt >> 1][(nt & 1) * 2],
                            bH[nt >> 1][(nt & 1) * 2 + 1]);
        }
        __syncthreads();
    }

    const int g = lane >> 2, t2 = (lane & 3) * 2;
#pragma unroll
    for (int mt = 0; mt < 4; mt++) {
        int mrow = bm + wm * 64 + mt * 16 + g;
#pragma unroll
        for (int nt = 0; nt < 4; nt++) {
            int ncol = bn + wn * 32 + nt * 8 + t2;
            *(float2*)&C[(size_t)mrow * HIDDEN + ncol] =
                make_float2(acc[mt][nt][0], acc[mt][nt][1]);
            *(float2*)&C[(size_t)(mrow + 8) * HIDDEN + ncol] =
                make_float2(acc[mt][nt][2], acc[mt][nt][3]);
        }
    }
}

// --------- fused RoPE(q,k) + plain convert(v), all -> single fp16 ----------
__global__ __launch_bounds__(256) void rope_cvt_qkv() {
    int idx = blockIdx.x * blockDim.x + threadIdx.x;   // 3*4096*16*64
    int d = idx & 63;
    int h = (idx >> 6) & 15;
    int t = (idx >> 10) & (T_SEQ - 1);
    int w = idx >> 22;                                  // 0=q, 1=k, 2=v
    const float* src = g_qkv + (size_t)w * T_SEQ * HIDDEN
                     + (size_t)t * HIDDEN + h * HEAD_DIM;
    size_t o = (size_t)t * HIDDEN + h * HEAD_DIM;

    if (w == 2) {
        g_vh[o + d]      = __float2half(src[d]);
        g_vh[o + d + 64] = __float2half(src[d + 64]);
        return;
    }
    float inv_freq = powf(10000.0f, -(float)d * (1.0f / 64.0f));
    float ang = (float)t * inv_freq;
    float c = cosf(ang), s = sinf(ang);
    float x1 = src[d];
    float x2 = src[d + 64];
    float y1 = x1 * c - x2 * s;
    float y2 = x2 * c + x1 * s;
    __half* dst = (w == 0) ? g_qh : g_kh;
    dst[o + d]      = __float2half(y1);
    dst[o + d + 64] = __float2half(y2);
}

// ---------------- flash attention, single-pass fp16 ------------------------
// 256 threads (8 warps), BQ=128; 64-key tiles, 2-stage KV prefetch.
// smem: QH 0 (32KB); KV stage s at 32768 + s*32768: KH +0, VH +16384. 96KB.
#define AT_QH 0
#define AT_KV0 32768
#define AT_KVS 32768
#define AT_SMEM 98304

__global__ __launch_bounds__(256, 1) void flash_mma() {
    extern __shared__ char sm[];
    const uint32_t sb = smem_u32(sm);
    const int tid = threadIdx.x;
    const int lane = tid & 31;
    const int w = tid >> 5;
    const int h = blockIdx.y;
    const int qb = (gridDim.x - 1) - blockIdx.x;       // heavy blocks first

    const int g = lane >> 2, t4 = lane & 3;
    const int LAST = 2 * qb + 1;

    const int krow = tid >> 2, kcb = (tid & 3) * 4;

    auto issue_kv = [&](int kb) {
        uint32_t st = sb + AT_KV0 + (kb & 1) * AT_KVS;
        size_t gk = (size_t)(kb * 64 + krow) * HIDDEN + h * HEAD_DIM;
#pragma unroll
        for (int j = 0; j < 4; j++) {
            int c = kcb + j;
            uint32_t off = swz(krow, c * 16);
            cp_async16(st + 0     + off, g_kh + gk + c * 8);
            cp_async16(st + 16384 + off, g_vh + gk + c * 8);
        }
    };

    {
        int lrow = tid >> 1, cb2 = (tid & 1) * 8;
        size_t gq = (size_t)(qb * 128 + lrow) * HIDDEN + h * HEAD_DIM;
#pragma unroll
        for (int j = 0; j < 8; j++) {
            int c = cb2 + j;
            cp_async16(sb + AT_QH + swz(lrow, c * 16), g_qh + gq + c * 8);
        }
        issue_kv(0);
        CP_COMMIT();
    }

    float O[16][4];
#pragma unroll
    for (int i = 0; i < 16; i++)
#pragma unroll
        for (int c = 0; c < 4; c++) O[i][c] = 0.f;
    float den0 = 0.f, den1 = 0.f;
    uint32_t qF[8][4];

    const int aRow = w * 16 + (lane & 15);
    const int aHalf = (lane >> 4) * 16;
    const int bRowBase = ((lane >> 4) & 1) * 8 + (lane & 7);
    const int bHalf = ((lane >> 3) & 1) * 16;
    const int vRowBase = ((lane >> 3) & 1) * 8 + (lane & 7);
    const int vHalf = ((lane >> 4) & 1) * 16;

    for (int kb = 0; kb <= LAST; kb++) {
        if (kb + 1 <= LAST) { issue_kv(kb + 1); CP_COMMIT(); CP_WAIT1(); }
        else CP_WAIT0();
        __syncthreads();

        if (kb == 0) {
#pragma unroll
            for (int s = 0; s < 8; s++)
                ldmx4(qF[s], sb + AT_QH + swz(aRow, s * 32 + aHalf));
        }

        const uint32_t st = sb + AT_KV0 + (kb & 1) * AT_KVS;

        // ---- S = Q K^T (single pass) ----
        float S[8][4];
#pragma unroll
        for (int i = 0; i < 8; i++)
#pragma unroll
            for (int c = 0; c < 4; c++) S[i][c] = 0.f;

#pragma unroll
        for (int s = 0; s < 8; s++) {
            uint32_t bh[4][4];
#pragma unroll
            for (int p = 0; p < 4; p++)
                ldmx4(bh[p], st + swz(bRowBase + p * 16, s * 32 + bHalf));
#pragma unroll
            for (int p = 0; p < 4; p++)
#pragma unroll
                for (int hf = 0; hf < 2; hf++)
                    mma_f16(S[p * 2 + hf], qF[s], bh[p][hf * 2], bh[p][hf * 2 + 1]);
        }

        // ---- softcap + causal + exp ----
        const int rowg = qb * 128 + w * 16 + g;
        const bool diag = (kb >= 2 * qb);
#pragma unroll
        for (int nt = 0; nt < 8; nt++) {
#pragma unroll
            for (int c = 0; c < 4; c++) {
                float a = S[nt][c] * ATT_SCALE;
                float u = a * (2.0f / SOFTCAP);
                float e2 = __expf(u);
                float th = (e2 - 1.0f) / (e2 + 1.0f);
                float p = __expf(th * SOFTCAP);
                if (diag) {
                    int col = kb * 64 + nt * 8 + 2 * t4 + (c & 1);
                    int row = rowg + (c >> 1) * 8;
                    if (col > row) p = 0.f;
                }
                S[nt][c] = p;
                if (c < 2) den0 += p; else den1 += p;
            }
        }

        uint32_t pH[4][4];
#pragma unroll
        for (int s2 = 0; s2 < 4; s2++) {
            pH[s2][0] = pack_h2(S[2*s2][0],   S[2*s2][1]);
            pH[s2][1] = pack_h2(S[2*s2][2],   S[2*s2][3]);
            pH[s2][2] = pack_h2(S[2*s2+1][0], S[2*s2+1][1]);
            pH[s2][3] = pack_h2(S[2*s2+1][2], S[2*s2+1][3]);
        }

        // ---- O += P V (single pass) ----
#pragma unroll
        for (int s2 = 0; s2 < 4; s2++) {
            int vRow = s2 * 16 + vRowBase;
#pragma unroll
            for (int dp = 0; dp < 8; dp++) {
                uint32_t vh4[4];
                ldmx4t(vh4, st + 16384 + swz(vRow, dp * 32 + vHalf));
#pragma unroll
                for (int hf = 0; hf < 2; hf++)
                    mma_f16(O[dp * 2 + hf], pH[s2], vh4[hf * 2], vh4[hf * 2 + 1]);
            }
        }
        __syncthreads();
    }

    den0 += __shfl_xor_sync(0xFFFFFFFF, den0, 1);
    den0 += __shfl_xor_sync(0xFFFFFFFF, den0, 2);
    den1 += __shfl_xor_sync(0xFFFFFFFF, den1, 1);
    den1 += __shfl_xor_sync(0xFFFFFFFF, den1, 2);
    float inv0 = 1.0f / den0, inv1 = 1.0f / den1;

    const int row0 = qb * 128 + w * 16 + g;
    uint32_t* ahp = (uint32_t*)g_ah;
#pragma unroll
    for (int dt = 0; dt < 16; dt++) {
        int col = h * HEAD_DIM + dt * 8 + 2 * t4;
        size_t o0 = ((size_t)row0 * HIDDEN + col) >> 1;
        size_t o1 = ((size_t)(row0 + 8) * HIDDEN + col) >> 1;
        ahp[o0] = pack_h2(O[dt][0] * inv0, O[dt][1] * inv0);
        ahp[o1] = pack_h2(O[dt][2] * inv1, O[dt][3] * inv1);
    }
}

// ---------------- launch ----------------------------------------------------
extern "C" void kernel_launch(void* const* d_in, const int* in_sizes, int n_in,
                              void* d_out, int out_size) {
    const float* X  = (const float*)d_in[0];
    const float* Wq = (const float*)d_in[1];
    const float* Wk = (const float*)d_in[2];
    const float* Wv = (const float*)d_in[3];
    const float* Wo = (const float*)d_in[4];
    float* out = (float*)d_out;

    float* qkv; cudaGetSymbolAddress((void**)&qkv, g_qkv);
    __half *xh, *ah, *wth;
    cudaGetSymbolAddress((void**)&xh, g_xh);
    cudaGetSymbolAddress((void**)&ah, g_ah);
    cudaGetSymbolAddress((void**)&wth, g_wth);

    cudaFuncSetAttribute(gemm_mma, cudaFuncAttributeMaxDynamicSharedMemorySize, GS_TOTAL);
    cudaFuncSetAttribute(flash_mma, cudaFuncAttributeMaxDynamicSharedMemorySize, AT_SMEM);

    const size_t WSTRIDE = (size_t)HIDDEN * HIDDEN;

    transpose_half4<<<dim3(HIDDEN / 32, HIDDEN / 32, 4), dim3(32, 8)>>>(Wq, Wk, Wv, Wo, wth);
    cvt_half<<<(T_SEQ * HIDDEN) / 1024, 256>>>(X, xh);

    // fused QKV: z selects weight & output
    gemm_mma<<<dim3(HIDDEN / 128, T_SEQ / 128, 3), 256, GS_TOTAL>>>(
        xh, wth, qkv, WSTRIDE, (size_t)T_SEQ * HIDDEN);

    rope_cvt_qkv<<<(3u * T_SEQ * NHEADS * 64) / 256, 256>>>();

    flash_mma<<<dim3(T_SEQ / 128, NHEADS), 256, AT_SMEM>>>();

    gemm_mma<<<dim3(HIDDEN / 128, T_SEQ / 128, 1), 256, GS_TOTAL>>>(
        ah, wth + 3 * WSTRIDE, out, 0, 0);
}

// round 10
// speedup vs baseline: 9.5441x; 1.3966x over previous
#include <cuda_runtime.h>
#include <cuda_fp16.h>
#include <cstdint>
#include <math.h>

#define T_SEQ 4096
#define HIDDEN 2048
#define NHEADS 16
#define HEAD_DIM 128
#define SOFTCAP 50.0f
#define ATT_SCALE 0.0625f   // 256^-0.5

// ---------------- scratch (device globals; allocation-free) ----------------
__device__ __half g_xh[(size_t)T_SEQ * HIDDEN];      // X in fp16
__device__ __half g_ah[(size_t)T_SEQ * HIDDEN];      // attention out (fp16)
__device__ __half g_wth[4u * HIDDEN * HIDDEN];       // transposed weights (fp16)
__device__ __half g_qkvh[3u * T_SEQ * HIDDEN];       // q,k,v fp16 (roped in place)

// ======================= PTX helpers =======================================
__device__ __forceinline__ uint32_t smem_u32(const void* p) {
    uint32_t a;
    asm("{ .reg .u64 t; cvta.to.shared.u64 t, %1; cvt.u32.u64 %0, t; }"
        : "=r"(a) : "l"(p));
    return a;
}
__device__ __forceinline__ void cp_async16(uint32_t s, const void* g) {
    asm volatile("cp.async.cg.shared.global [%0], [%1], 16;" :: "r"(s), "l"(g));
}
#define CP_COMMIT() asm volatile("cp.async.commit_group;" ::: "memory")
#define CP_WAIT1()  asm volatile("cp.async.wait_group 1;" ::: "memory")
#define CP_WAIT0()  asm volatile("cp.async.wait_group 0;" ::: "memory")

__device__ __forceinline__ void ldmx4(uint32_t* r, uint32_t addr) {
    asm volatile("ldmatrix.sync.aligned.m8n8.x4.shared.b16 {%0,%1,%2,%3}, [%4];"
        : "=r"(r[0]), "=r"(r[1]), "=r"(r[2]), "=r"(r[3]) : "r"(addr));
}
__device__ __forceinline__ void ldmx4t(uint32_t* r, uint32_t addr) {
    asm volatile("ldmatrix.sync.aligned.m8n8.x4.trans.shared.b16 {%0,%1,%2,%3}, [%4];"
        : "=r"(r[0]), "=r"(r[1]), "=r"(r[2]), "=r"(r[3]) : "r"(addr));
}
__device__ __forceinline__ void mma_f16(float* d, const uint32_t* a,
                                        uint32_t b0, uint32_t b1) {
    asm volatile("mma.sync.aligned.m16n8k16.row.col.f32.f16.f16.f32 "
        "{%0,%1,%2,%3}, {%4,%5,%6,%7}, {%8,%9}, {%0,%1,%2,%3};"
        : "+f"(d[0]), "+f"(d[1]), "+f"(d[2]), "+f"(d[3])
        : "r"(a[0]), "r"(a[1]), "r"(a[2]), "r"(a[3]), "r"(b0), "r"(b1));
}
__device__ __forceinline__ uint32_t pack_h2(float lo, float hi) {
    __half2 v;
    v.x = __float2half(lo);
    v.y = __float2half(hi);
    return *(uint32_t*)&v;
}
__device__ __forceinline__ uint32_t swz(int row, int cb) {
    return (uint32_t)(row * 256 + (cb ^ ((row & 7) * 16)));
}

// ---------------- conversions ----------------------------------------------
__global__ __launch_bounds__(256) void cvt_half(const float* __restrict__ in,
                                                __half* __restrict__ oh) {
    int i = (blockIdx.x * 256 + threadIdx.x) * 4;
    float4 v = *(const float4*)&in[i];
    oh[i + 0] = __float2half(v.x);
    oh[i + 1] = __float2half(v.y);
    oh[i + 2] = __float2half(v.z);
    oh[i + 3] = __float2half(v.w);
}

// fused 4-way transpose 2048x2048 fp32 -> fp16 at [n][k]; z selects matrix
__global__ __launch_bounds__(256) void transpose_half4(
    const float* __restrict__ w0, const float* __restrict__ w1,
    const float* __restrict__ w2, const float* __restrict__ w3,
    __half* __restrict__ out)
{
    __shared__ float t[32][33];
    const float* in = (blockIdx.z == 0) ? w0 : (blockIdx.z == 1) ? w1
                    : (blockIdx.z == 2) ? w2 : w3;
    __half* o = out + (size_t)blockIdx.z * HIDDEN * HIDDEN;
    int x = blockIdx.x * 32 + threadIdx.x;
    int y = blockIdx.y * 32 + threadIdx.y;
#pragma unroll
    for (int j = 0; j < 4; j++)
        t[threadIdx.y + 8 * j][threadIdx.x] = in[(size_t)(y + 8 * j) * HIDDEN + x];
    __syncthreads();
    x = blockIdx.y * 32 + threadIdx.x;
    y = blockIdx.x * 32 + threadIdx.y;
#pragma unroll
    for (int j = 0; j < 4; j++)
        o[(size_t)(y + 8 * j) * HIDDEN + x] = __float2half(t[threadIdx.x][threadIdx.y + 8 * j]);
}

// ---------------- fp16 single-pass mma GEMM --------------------------------
// C[z] = A @ B[z]^T.  Output: fp16 (Ch0 != 0) or fp32 (C0).
// Tile 128x128, BK=32, 2-stage cp.async; 8 warps (2m x 4n).
#define GS_AH 0
#define GS_BH 10240
#define GS_STAGE 20480
#define GS_TOTAL (2 * GS_STAGE)
#define G_KCHUNKS (HIDDEN / 32)

__global__ __launch_bounds__(256, 2) void gemm_mma(
    const __half* __restrict__ Ah,
    const __half* __restrict__ B0,
    float* __restrict__ C0, __half* __restrict__ Ch0,
    size_t bStrideZ, size_t cStrideZ)
{
    extern __shared__ char sm[];
    const uint32_t sb = smem_u32(sm);
    const int tid = threadIdx.x;
    const int lane = tid & 31;
    const int wid = tid >> 5;
    const int wm = wid & 1;
    const int wn = wid >> 1;
    const int bm = blockIdx.y * 128;
    const int bn = blockIdx.x * 128;
    const __half* B = B0 + (size_t)blockIdx.z * bStrideZ;

    float acc[4][4][4];
#pragma unroll
    for (int a = 0; a < 4; a++)
#pragma unroll
        for (int b = 0; b < 4; b++)
#pragma unroll
            for (int c = 0; c < 4; c++) acc[a][b][c] = 0.f;

    auto issue = [&](int chunk) {
        uint32_t st = sb + (chunk & 1) * GS_STAGE;
        int k0 = chunk * 32;
#pragma unroll
        for (int p = 0; p < 2; p++) {
            int idx = tid + p * 256;
            int row = idx >> 2, c = idx & 3;
            uint32_t soff = row * 80 + c * 16;
            size_t ga = (size_t)(bm + row) * HIDDEN + k0 + c * 8;
            size_t gb = (size_t)(bn + row) * HIDDEN + k0 + c * 8;
            cp_async16(st + GS_AH + soff, Ah + ga);
            cp_async16(st + GS_BH + soff, B + gb);
        }
    };

    const uint32_t aBase = (uint32_t)(wm * 64 + (lane & 15)) * 80 + (lane >> 4) * 16;
    const uint32_t bBase = (uint32_t)(wn * 32 + ((lane >> 4) & 1) * 8 + (lane & 7)) * 80
                         + ((lane >> 3) & 1) * 16;

    issue(0); CP_COMMIT();

    for (int i = 0; i < G_KCHUNKS; i++) {
        if (i + 1 < G_KCHUNKS) { issue(i + 1); CP_COMMIT(); CP_WAIT1(); }
        else CP_WAIT0();
        __syncthreads();
        uint32_t st = sb + (i & 1) * GS_STAGE;
#pragma unroll
        for (int kk = 0; kk < 2; kk++) {
            uint32_t aH[4][4], bH[2][4];
#pragma unroll
            for (int mt = 0; mt < 4; mt++)
                ldmx4(aH[mt], st + GS_AH + aBase + mt * 1280 + kk * 32);
#pragma unroll
            for (int np = 0; np < 2; np++)
                ldmx4(bH[np], st + GS_BH + bBase + np * 1280 + kk * 32);
#pragma unroll
            for (int mt = 0; mt < 4; mt++)
#pragma unroll
                for (int nt = 0; nt < 4; nt++)
                    mma_f16(acc[mt][nt], aH[mt],
                            bH[nt >> 1][(nt & 1) * 2],
                            bH[nt >> 1][(nt & 1) * 2 + 1]);
        }
        __syncthreads();
    }

    const int g = lane >> 2, t2 = (lane & 3) * 2;
    if (Ch0) {
        __half* C = Ch0 + (size_t)blockIdx.z * cStrideZ;
        uint32_t* Cp = (uint32_t*)C;
#pragma unroll
        for (int mt = 0; mt < 4; mt++) {
            int mrow = bm + wm * 64 + mt * 16 + g;
#pragma unroll
            for (int nt = 0; nt < 4; nt++) {
                int ncol = bn + wn * 32 + nt * 8 + t2;
                Cp[((size_t)mrow * HIDDEN + ncol) >> 1] =
                    pack_h2(acc[mt][nt][0], acc[mt][nt][1]);
                Cp[((size_t)(mrow + 8) * HIDDEN + ncol) >> 1] =
                    pack_h2(acc[mt][nt][2], acc[mt][nt][3]);
            }
        }
    } else {
        float* C = C0 + (size_t)blockIdx.z * cStrideZ;
#pragma unroll
        for (int mt = 0; mt < 4; mt++) {
            int mrow = bm + wm * 64 + mt * 16 + g;
#pragma unroll
            for (int nt = 0; nt < 4; nt++) {
                int ncol = bn + wn * 32 + nt * 8 + t2;
                *(float2*)&C[(size_t)mrow * HIDDEN + ncol] =
                    make_float2(acc[mt][nt][0], acc[mt][nt][1]);
                *(float2*)&C[(size_t)(mrow + 8) * HIDDEN + ncol] =
                    make_float2(acc[mt][nt][2], acc[mt][nt][3]);
            }
        }
    }
}

// --------- in-place fp16 RoPE on q,k (half2-vectorized) --------------------
__global__ __launch_bounds__(256) void rope_qk() {
    int idx = blockIdx.x * blockDim.x + threadIdx.x;   // 2*4096*16*32
    int d2 = idx & 31;                                  // half2 pair: d = 2*d2, 2*d2+1
    int h  = (idx >> 5) & 15;
    int t  = (idx >> 9) & (T_SEQ - 1);
    int w  = idx >> 21;                                 // 0=q, 1=k
    __half* base = g_qkvh + (size_t)w * T_SEQ * HIDDEN
                 + (size_t)t * HIDDEN + h * HEAD_DIM;

    int d0 = 2 * d2;
    float f0 = powf(10000.0f, -(float)d0 * (1.0f / 64.0f));
    float f1 = f0 * 0.86596432f;                        // * 10000^(-1/64)
    float c0, s0, c1, s1;
    sincosf((float)t * f0, &s0, &c0);
    sincosf((float)t * f1, &s1, &c1);

    __half2 lo = *(__half2*)(base + d0);
    __half2 hi = *(__half2*)(base + d0 + 64);
    float x1a = __half2float(lo.x), x1b = __half2float(lo.y);
    float x2a = __half2float(hi.x), x2b = __half2float(hi.y);

    *(uint32_t*)(base + d0)      = pack_h2(x1a * c0 - x2a * s0, x1b * c1 - x2b * s1);
    *(uint32_t*)(base + d0 + 64) = pack_h2(x2a * c0 + x1a * s0, x2b * c1 + x1b * s1);
}

// ---------------- flash attention, single-pass fp16 ------------------------
// 256 threads (8 warps), BQ=128; 64-key tiles, 2-stage KV prefetch.
// smem: QH 0 (32KB); KV stage s at 32768 + s*32768: KH +0, VH +16384. 96KB.
#define AT_QH 0
#define AT_KV0 32768
#define AT_KVS 32768
#define AT_SMEM 98304

// softcap constants:  p = 2^(E0 - E1 * 1/(e^{2a/50}+1)),  a = s*ATT_SCALE
#define SC_C1 0.0036067376f    /* ATT_SCALE * (2/50) * log2(e) */
#define SC_E0 72.134752f       /* 50 * log2(e) */
#define SC_E1 144.269504f      /* 100 * log2(e) */

__global__ __launch_bounds__(256, 1) void flash_mma() {
    extern __shared__ char sm[];
    const uint32_t sb = smem_u32(sm);
    const int tid = threadIdx.x;
    const int lane = tid & 31;
    const int w = tid >> 5;
    const int h = blockIdx.y;
    const int qb = (gridDim.x - 1) - blockIdx.x;       // heavy blocks first

    const __half* Qg = g_qkvh;
    const __half* Kg = g_qkvh + (size_t)T_SEQ * HIDDEN;
    const __half* Vg = g_qkvh + 2u * T_SEQ * HIDDEN;

    const int g = lane >> 2, t4 = lane & 3;
    const int LAST = 2 * qb + 1;

    const int krow = tid >> 2, kcb = (tid & 3) * 4;

    auto issue_kv = [&](int kb) {
        uint32_t st = sb + AT_KV0 + (kb & 1) * AT_KVS;
        size_t gk = (size_t)(kb * 64 + krow) * HIDDEN + h * HEAD_DIM;
#pragma unroll
        for (int j = 0; j < 4; j++) {
            int c = kcb + j;
            uint32_t off = swz(krow, c * 16);
            cp_async16(st + 0     + off, Kg + gk + c * 8);
            cp_async16(st + 16384 + off, Vg + gk + c * 8);
        }
    };

    {
        int lrow = tid >> 1, cb2 = (tid & 1) * 8;
        size_t gq = (size_t)(qb * 128 + lrow) * HIDDEN + h * HEAD_DIM;
#pragma unroll
        for (int j = 0; j < 8; j++) {
            int c = cb2 + j;
            cp_async16(sb + AT_QH + swz(lrow, c * 16), Qg + gq + c * 8);
        }
        issue_kv(0);
        CP_COMMIT();
    }

    float O[16][4];
#pragma unroll
    for (int i = 0; i < 16; i++)
#pragma unroll
        for (int c = 0; c < 4; c++) O[i][c] = 0.f;
    float den0 = 0.f, den1 = 0.f;
    uint32_t qF[8][4];

    const int aRow = w * 16 + (lane & 15);
    const int aHalf = (lane >> 4) * 16;
    const int bRowBase = ((lane >> 4) & 1) * 8 + (lane & 7);
    const int bHalf = ((lane >> 3) & 1) * 16;
    const int vRowBase = ((lane >> 3) & 1) * 8 + (lane & 7);
    const int vHalf = ((lane >> 4) & 1) * 16;

    for (int kb = 0; kb <= LAST; kb++) {
        if (kb + 1 <= LAST) { issue_kv(kb + 1); CP_COMMIT(); CP_WAIT1(); }
        else CP_WAIT0();
        __syncthreads();

        if (kb == 0) {
#pragma unroll
            for (int s = 0; s < 8; s++)
                ldmx4(qF[s], sb + AT_QH + swz(aRow, s * 32 + aHalf));
        }

        const uint32_t st = sb + AT_KV0 + (kb & 1) * AT_KVS;

        // ---- S = Q K^T ----
        float S[8][4];
#pragma unroll
        for (int i = 0; i < 8; i++)
#pragma unroll
            for (int c = 0; c < 4; c++) S[i][c] = 0.f;

#pragma unroll
        for (int s = 0; s < 8; s++) {
            uint32_t bh[4][4];
#pragma unroll
            for (int p = 0; p < 4; p++)
                ldmx4(bh[p], st + swz(bRowBase + p * 16, s * 32 + bHalf));
#pragma unroll
            for (int p = 0; p < 4; p++)
#pragma unroll
                for (int hf = 0; hf < 2; hf++)
                    mma_f16(S[p * 2 + hf], qF[s], bh[p][hf * 2], bh[p][hf * 2 + 1]);
        }

        // ---- softcap + causal + exp (exp2 identity) ----
        const int rowg = qb * 128 + w * 16 + g;
        const bool diag = (kb >= 2 * qb);
#pragma unroll
        for (int nt = 0; nt < 8; nt++) {
#pragma unroll
            for (int c = 0; c < 4; c++) {
                float e2 = exp2f(S[nt][c] * SC_C1);
                float r = __fdividef(1.0f, e2 + 1.0f);
                float p = exp2f(SC_E0 - SC_E1 * r);
                if (diag) {
                    int col = kb * 64 + nt * 8 + 2 * t4 + (c & 1);
                    int row = rowg + (c >> 1) * 8;
                    if (col > row) p = 0.f;
                }
                S[nt][c] = p;
                if (c < 2) den0 += p; else den1 += p;
            }
        }

        uint32_t pH[4][4];
#pragma unroll
        for (int s2 = 0; s2 < 4; s2++) {
            pH[s2][0] = pack_h2(S[2*s2][0],   S[2*s2][1]);
            pH[s2][1] = pack_h2(S[2*s2][2],   S[2*s2][3]);
            pH[s2][2] = pack_h2(S[2*s2+1][0], S[2*s2+1][1]);
            pH[s2][3] = pack_h2(S[2*s2+1][2], S[2*s2+1][3]);
        }

        // ---- O += P V ----
#pragma unroll
        for (int s2 = 0; s2 < 4; s2++) {
            int vRow = s2 * 16 + vRowBase;
#pragma unroll
            for (int dp = 0; dp < 8; dp++) {
                uint32_t vh4[4];
                ldmx4t(vh4, st + 16384 + swz(vRow, dp * 32 + vHalf));
#pragma unroll
                for (int hf = 0; hf < 2; hf++)
                    mma_f16(O[dp * 2 + hf], pH[s2], vh4[hf * 2], vh4[hf * 2 + 1]);
            }
        }
        __syncthreads();
    }

    den0 += __shfl_xor_sync(0xFFFFFFFF, den0, 1);
    den0 += __shfl_xor_sync(0xFFFFFFFF, den0, 2);
    den1 += __shfl_xor_sync(0xFFFFFFFF, den1, 1);
    den1 += __shfl_xor_sync(0xFFFFFFFF, den1, 2);
    float inv0 = 1.0f / den0, inv1 = 1.0f / den1;

    const int row0 = qb * 128 + w * 16 + g;
    uint32_t* ahp = (uint32_t*)g_ah;
#pragma unroll
    for (int dt = 0; dt < 16; dt++) {
        int col = h * HEAD_DIM + dt * 8 + 2 * t4;
        size_t o0 = ((size_t)row0 * HIDDEN + col) >> 1;
        size_t o1 = ((size_t)(row0 + 8) * HIDDEN + col) >> 1;
        ahp[o0] = pack_h2(O[dt][0] * inv0, O[dt][1] * inv0);
        ahp[o1] = pack_h2(O[dt][2] * inv1, O[dt][3] * inv1);
    }
}

// ---------------- launch ----------------------------------------------------
extern "C" void kernel_launch(void* const* d_in, const int* in_sizes, int n_in,
                              void* d_out, int out_size) {
    const float* X  = (const float*)d_in[0];
    const float* Wq = (const float*)d_in[1];
    const float* Wk = (const float*)d_in[2];
    const float* Wv = (const float*)d_in[3];
    const float* Wo = (const float*)d_in[4];
    float* out = (float*)d_out;

    __half *xh, *ah, *wth, *qkvh;
    cudaGetSymbolAddress((void**)&xh, g_xh);
    cudaGetSymbolAddress((void**)&ah, g_ah);
    cudaGetSymbolAddress((void**)&wth, g_wth);
    cudaGetSymbolAddress((void**)&qkvh, g_qkvh);

    cudaFuncSetAttribute(gemm_mma, cudaFuncAttributeMaxDynamicSharedMemorySize, GS_TOTAL);
    cudaFuncSetAttribute(flash_mma, cudaFuncAttributeMaxDynamicSharedMemorySize, AT_SMEM);

    const size_t WSTRIDE = (size_t)HIDDEN * HIDDEN;

    transpose_half4<<<dim3(HIDDEN / 32, HIDDEN / 32, 4), dim3(32, 8)>>>(Wq, Wk, Wv, Wo, wth);
    cvt_half<<<(T_SEQ * HIDDEN) / 1024, 256>>>(X, xh);

    // fused QKV, fp16 output directly into g_qkvh
    gemm_mma<<<dim3(HIDDEN / 128, T_SEQ / 128, 3), 256, GS_TOTAL>>>(
        xh, wth, nullptr, qkvh, WSTRIDE, (size_t)T_SEQ * HIDDEN);

    rope_qk<<<(2u * T_SEQ * NHEADS * 32) / 256, 256>>>();

    flash_mma<<<dim3(T_SEQ / 128, NHEADS), 256, AT_SMEM>>>();

    // Wo GEMM, fp32 output to harness buffer
    gemm_mma<<<dim3(HIDDEN / 128, T_SEQ / 128, 1), 256, GS_TOTAL>>>(
        ah, wth + 3 * WSTRIDE, out, nullptr, 0, 0);
}